// round 1
// baseline (speedup 1.0000x reference)
#include <cuda_runtime.h>
#include <cuda_bf16.h>
#include <math.h>

// Problem dims (fixed)
#define NN 2048
#define DD 512
#define HH 256
#define LL 16
#define L2 32

#define OFF_MU (NN * NN)
#define OFF_LV (NN * NN + NN * LL)

// Scratch (device globals; no allocation allowed)
__device__ float g_Y[NN * HH];      // X @ W1^T
__device__ float g_Hh[NN * HH];     // leaky(A @ Y + b1)
__device__ float g_G[NN * L2];      // Hh @ [Wmu;Wlv]^T
__device__ float g_MLp[4][NN * L2]; // split-K partials of A @ G
__device__ float g_P[NN * L2];      // Z @ Wd1[:, :16]^T
__device__ float g_Qb[NN * L2];     // Z @ Wd1[:, 16:]^T + bd1

// ---------------------------------------------------------------------------
// Generic 64x64 SGEMM, 256 threads, 4x4 micro-tile, BK=16, global prefetch.
// BT=false: C[M,N] = A[M,K] @ B[K,N]
// BT=true : C[M,N] = A[M,K] @ B'[N,K]^T   (B stored row-major [N,K])
// LEAKY   : C = leaky_relu(C + bias[n])
// ---------------------------------------------------------------------------
template <bool BT, bool LEAKY>
__global__ __launch_bounds__(256) void sgemm64(
    const float* __restrict__ A, const float* __restrict__ B,
    float* __restrict__ C, int M, int N, int K,
    const float* __restrict__ bias)
{
    __shared__ float As[16][68];
    __shared__ float Bs[16][68];

    const int tid = threadIdx.x;
    const int m0 = blockIdx.y * 64;
    const int n0 = blockIdx.x * 64;

    // A loader: 64 rows x 16 cols, float4 per thread, stored transposed
    const int ar = tid >> 2;
    const int ac = (tid & 3) << 2;
    const float* Aptr = A + (size_t)(m0 + ar) * K + ac;

    // B loader
    int br, bc;
    const float* Bptr;
    if (BT) {
        br = tid >> 2; bc = (tid & 3) << 2;           // br = n-local, bc = k-local
        Bptr = B + (size_t)(n0 + br) * K + bc;
    } else {
        br = tid >> 4; bc = (tid & 15) << 2;          // br = k-local, bc = n-local
        Bptr = B + (size_t)br * N + n0 + bc;
    }

    const int tx = tid & 15;
    const int ty = tid >> 4;

    float acc[4][4] = {};

    float4 aR = *(const float4*)Aptr;
    float4 bR = *(const float4*)Bptr;

    for (int kt = 0; kt < K; kt += 16) {
        // stage to smem
        As[ac + 0][ar] = aR.x; As[ac + 1][ar] = aR.y;
        As[ac + 2][ar] = aR.z; As[ac + 3][ar] = aR.w;
        if (BT) {
            Bs[bc + 0][br] = bR.x; Bs[bc + 1][br] = bR.y;
            Bs[bc + 2][br] = bR.z; Bs[bc + 3][br] = bR.w;
        } else {
            *(float4*)&Bs[br][bc] = bR;
        }
        __syncthreads();

        // prefetch next tile
        if (kt + 16 < K) {
            aR = *(const float4*)(Aptr + kt + 16);
            bR = BT ? *(const float4*)(Bptr + kt + 16)
                    : *(const float4*)(Bptr + (size_t)(kt + 16) * N);
        }

        #pragma unroll
        for (int kk = 0; kk < 16; kk++) {
            float4 av = *(const float4*)&As[kk][ty * 4];
            float4 bv = *(const float4*)&Bs[kk][tx * 4];
            float a_[4] = {av.x, av.y, av.z, av.w};
            float b_[4] = {bv.x, bv.y, bv.z, bv.w};
            #pragma unroll
            for (int i = 0; i < 4; i++)
                #pragma unroll
                for (int j = 0; j < 4; j++)
                    acc[i][j] = fmaf(a_[i], b_[j], acc[i][j]);
        }
        __syncthreads();
    }

    float4 bv = LEAKY ? *(const float4*)&bias[n0 + tx * 4]
                      : make_float4(0.f, 0.f, 0.f, 0.f);
    float bb[4] = {bv.x, bv.y, bv.z, bv.w};

    #pragma unroll
    for (int i = 0; i < 4; i++) {
        int row = m0 + ty * 4 + i;
        float v[4];
        #pragma unroll
        for (int j = 0; j < 4; j++) {
            float t = acc[i][j];
            if (LEAKY) { t += bb[j]; t = fmaxf(t, 0.01f * t); }
            v[j] = t;
        }
        *(float4*)&C[(size_t)row * N + n0 + tx * 4] =
            make_float4(v[0], v[1], v[2], v[3]);
    }
}

// ---------------------------------------------------------------------------
// K3: G[n, c] = sum_k Hh[n,k] * Wcat[c,k]; Wcat = [Wmu; Wlv] (32 x 256)
// block: 512 threads = 16 warps, each warp handles one row n, lanes = c
// ---------------------------------------------------------------------------
__global__ __launch_bounds__(512) void k3_gmat(
    const float* __restrict__ Wmu, const float* __restrict__ Wlv)
{
    __shared__ float Ws[32][257];
    const int tid = threadIdx.x;
    for (int idx = tid; idx < 32 * 256; idx += 512) {
        int c = idx >> 8, k = idx & 255;
        Ws[c][k] = (c < 16) ? Wmu[c * 256 + k] : Wlv[(c - 16) * 256 + k];
    }
    __syncthreads();

    const int m = blockIdx.x * 16 + (tid >> 5);
    const int c = tid & 31;
    const float4* hrow = (const float4*)&g_Hh[(size_t)m * 256];
    float acc = 0.f;
    #pragma unroll 4
    for (int k4 = 0; k4 < 64; k4++) {
        float4 h = hrow[k4];
        acc = fmaf(h.x, Ws[c][k4 * 4 + 0], acc);
        acc = fmaf(h.y, Ws[c][k4 * 4 + 1], acc);
        acc = fmaf(h.z, Ws[c][k4 * 4 + 2], acc);
        acc = fmaf(h.w, Ws[c][k4 * 4 + 3], acc);
    }
    g_G[m * 32 + c] = acc;
}

// ---------------------------------------------------------------------------
// K4: MLp[s] = A[:, sK:(s+1)K] @ G[sK:(s+1)K, :]  (split-K over 4 slices)
// tile 32 rows x 32 cols; lane = col c, warp -> 4 rows
// ---------------------------------------------------------------------------
__global__ __launch_bounds__(256) void k4_ag(const float* __restrict__ A)
{
    __shared__ float As[32][33];
    __shared__ float Gs[32][33];
    const int tid = threadIdx.x;
    const int lane = tid & 31;      // col c
    const int w = tid >> 5;         // rows w, w+8, w+16, w+24
    const int m0 = blockIdx.x * 32;
    const int k0base = blockIdx.y * 512;

    float acc[4] = {0.f, 0.f, 0.f, 0.f};
    for (int kt = 0; kt < 512; kt += 32) {
        const int k0 = k0base + kt;
        int i = tid * 4;
        int r = i >> 5, c = i & 31;
        float4 a4 = *(const float4*)&A[(size_t)(m0 + r) * NN + k0 + c];
        As[r][c] = a4.x; As[r][c + 1] = a4.y; As[r][c + 2] = a4.z; As[r][c + 3] = a4.w;
        float4 g4 = *(const float4*)&g_G[(size_t)(k0 + r) * 32 + c];
        Gs[r][c] = g4.x; Gs[r][c + 1] = g4.y; Gs[r][c + 2] = g4.z; Gs[r][c + 3] = g4.w;
        __syncthreads();
        #pragma unroll
        for (int kk = 0; kk < 32; kk++) {
            float g = Gs[kk][lane];
            acc[0] = fmaf(As[w +  0][kk], g, acc[0]);
            acc[1] = fmaf(As[w +  8][kk], g, acc[1]);
            acc[2] = fmaf(As[w + 16][kk], g, acc[2]);
            acc[3] = fmaf(As[w + 24][kk], g, acc[3]);
        }
        __syncthreads();
    }
    #pragma unroll
    for (int j = 0; j < 4; j++)
        g_MLp[blockIdx.y][(size_t)(m0 + w + 8 * j) * 32 + lane] = acc[j];
}

// ---------------------------------------------------------------------------
// K5: reduce split-K, add biases, write mu/logvar, reparameterize,
//     compute P and Qb(=Q+bd1). block = 8 rows x 32 lanes
// ---------------------------------------------------------------------------
__global__ __launch_bounds__(256) void k5_epi(
    const float* __restrict__ eps, const float* __restrict__ bmu,
    const float* __restrict__ blv, const float* __restrict__ Wd1,
    const float* __restrict__ bd1, float* __restrict__ out)
{
    __shared__ float mls[8][32];
    __shared__ float zs[8][16];
    const int r = threadIdx.x >> 5;
    const int c = threadIdx.x & 31;
    const int n = blockIdx.x * 8 + r;
    const size_t o = (size_t)n * 32 + c;

    float v = g_MLp[0][o] + g_MLp[1][o] + g_MLp[2][o] + g_MLp[3][o];
    if (c < 16) {
        v += bmu[c];
        out[OFF_MU + n * 16 + c] = v;
    } else {
        v += blv[c - 16];
        out[OFF_LV + n * 16 + (c - 16)] = v;
    }
    mls[r][c] = v;
    __syncthreads();

    if (c < 16) {
        float z = mls[r][c] + eps[n * 16 + c] * expf(0.5f * mls[r][16 + c]);
        zs[r][c] = z;
    }
    __syncthreads();

    float p = 0.f, q = 0.f;
    #pragma unroll
    for (int l = 0; l < 16; l++) {
        float z = zs[r][l];
        p = fmaf(z, Wd1[c * 32 + l], p);
        q = fmaf(z, Wd1[c * 32 + 16 + l], q);
    }
    g_P[o] = p;
    g_Qb[o] = q + bd1[c];
}

// ---------------------------------------------------------------------------
// Software sigmoid: no MUFU (EX2/RCP at rt 8/SMSP would cost ~60us for 4.2M)
// ---------------------------------------------------------------------------
__device__ __forceinline__ float fast_sigmoid(float x)
{
    float ax = fminf(fabsf(x), 30.0f);
    float t = ax * -1.4426950408889634f;     // log2(e^{-|x|}) in [-43.3, 0]
    float tr = t + 12582912.0f;              // round-to-nearest via magic
    int ki = __float_as_int(tr) - 0x4B400000;
    float f = t - (tr - 12582912.0f);        // frac in [-0.5, 0.5]
    // 2^f, degree-5 Taylor (rel err ~2.4e-6)
    float p = 1.3333558e-3f;
    p = fmaf(p, f, 9.6181291e-3f);
    p = fmaf(p, f, 5.5504109e-2f);
    p = fmaf(p, f, 2.4022651e-1f);
    p = fmaf(p, f, 6.9314718e-1f);
    p = fmaf(p, f, 1.0f);
    float rr = p * __int_as_float((ki + 127) << 23);  // e^{-|x|} in (0, 1]
    float d = 1.0f + rr;                              // [1, 2]
    float y = __int_as_float(0x7EF311C3 - __float_as_int(d));
    y = y * (2.0f - d * y);
    y = y * (2.0f - d * y);
    y = y * (2.0f - d * y);                           // 1/(1+e^{-|x|})
    return (x >= 0.0f) ? y : rr * y;
}

// ---------------------------------------------------------------------------
// K6: decoder. 64x64 pair tile, 4x4 micro-tile per thread.
// A_pred[i,j] = sigmoid( sum_h leaky(P[i,h] + Qb[j,h]) * Wd2[h] + bd2 )
// ---------------------------------------------------------------------------
__global__ __launch_bounds__(256) void k6_decoder(
    float* __restrict__ out, const float* __restrict__ Wd2,
    const float* __restrict__ bd2)
{
    __shared__ float Ps[64][33];
    __shared__ float Qs[64][33];
    __shared__ float ws[32];
    const int tid = threadIdx.x;
    const int i0 = blockIdx.y * 64;
    const int j0 = blockIdx.x * 64;

    {
        int idx = tid * 4;
        int r = idx >> 5, c = idx & 31;
        float4 p4 = *(const float4*)&g_P[(size_t)(i0 + r) * 32 + c];
        Ps[r][c] = p4.x; Ps[r][c + 1] = p4.y; Ps[r][c + 2] = p4.z; Ps[r][c + 3] = p4.w;
        float4 p5 = *(const float4*)&g_P[(size_t)(i0 + r + 32) * 32 + c];
        Ps[r + 32][c] = p5.x; Ps[r + 32][c + 1] = p5.y; Ps[r + 32][c + 2] = p5.z; Ps[r + 32][c + 3] = p5.w;
        float4 q4 = *(const float4*)&g_Qb[(size_t)(j0 + r) * 32 + c];
        Qs[r][c] = q4.x; Qs[r][c + 1] = q4.y; Qs[r][c + 2] = q4.z; Qs[r][c + 3] = q4.w;
        float4 q5 = *(const float4*)&g_Qb[(size_t)(j0 + r + 32) * 32 + c];
        Qs[r + 32][c] = q5.x; Qs[r + 32][c + 1] = q5.y; Qs[r + 32][c + 2] = q5.z; Qs[r + 32][c + 3] = q5.w;
    }
    if (tid < 32) ws[tid] = Wd2[tid];
    const float bd2v = bd2[0];
    __syncthreads();

    const int tx = tid & 15;
    const int ty = tid >> 4;
    float acc[4][4] = {};

    #pragma unroll
    for (int h = 0; h < 32; h++) {
        float w = ws[h];
        float pa[4], qb[4];
        #pragma unroll
        for (int u = 0; u < 4; u++) pa[u] = Ps[ty + 16 * u][h];
        #pragma unroll
        for (int v = 0; v < 4; v++) qb[v] = Qs[tx + 16 * v][h];
        #pragma unroll
        for (int u = 0; u < 4; u++)
            #pragma unroll
            for (int v = 0; v < 4; v++) {
                float t = pa[u] + qb[v];
                float lk = fmaxf(t, 0.01f * t);
                acc[u][v] = fmaf(lk, w, acc[u][v]);
            }
    }

    #pragma unroll
    for (int u = 0; u < 4; u++)
        #pragma unroll
        for (int v = 0; v < 4; v++)
            out[(size_t)(i0 + ty + 16 * u) * NN + (j0 + tx + 16 * v)] =
                fast_sigmoid(acc[u][v] + bd2v);
}

// ---------------------------------------------------------------------------
extern "C" void kernel_launch(void* const* d_in, const int* in_sizes, int n_in,
                              void* d_out, int out_size)
{
    const float* A_hat = (const float*)d_in[0];
    const float* X     = (const float*)d_in[1];
    const float* eps   = (const float*)d_in[2];
    const float* W1    = (const float*)d_in[3];
    const float* b1    = (const float*)d_in[4];
    const float* Wmu   = (const float*)d_in[5];
    const float* bmu   = (const float*)d_in[6];
    const float* Wlv   = (const float*)d_in[7];
    const float* blv   = (const float*)d_in[8];
    const float* Wd1   = (const float*)d_in[9];
    const float* bd1   = (const float*)d_in[10];
    const float* Wd2   = (const float*)d_in[11];
    const float* bd2   = (const float*)d_in[12];
    float* out = (float*)d_out;

    float* Y  = nullptr; cudaGetSymbolAddress((void**)&Y,  g_Y);
    float* Hh = nullptr; cudaGetSymbolAddress((void**)&Hh, g_Hh);

    // K1: Y = X @ W1^T        [2048,512]x[256,512]^T -> [2048,256]
    sgemm64<true, false><<<dim3(HH / 64, NN / 64), 256>>>(X, W1, Y, NN, HH, DD, nullptr);
    // K2: Hh = leaky(A @ Y + b1)   [2048,2048]x[2048,256]
    sgemm64<false, true><<<dim3(HH / 64, NN / 64), 256>>>(A_hat, Y, Hh, NN, HH, NN, b1);
    // K3: G = Hh @ [Wmu;Wlv]^T  -> [2048, 32]
    k3_gmat<<<NN / 16, 512>>>(Wmu, Wlv);
    // K4: ML partials = A @ G   (split-K x4)
    k4_ag<<<dim3(NN / 32, 4), 256>>>(A_hat);
    // K5: reduce + biases + mu/logvar out + Z + P/Qb
    k5_epi<<<NN / 8, 256>>>(eps, bmu, blv, Wd1, bd1, out);
    // K6: pairwise decoder -> A_pred
    k6_decoder<<<dim3(NN / 64, NN / 64), 256>>>(out, Wd2, bd2);
}

// round 2
// speedup vs baseline: 1.3254x; 1.3254x over previous
#include <cuda_runtime.h>
#include <cuda_bf16.h>
#include <math.h>

typedef unsigned long long ull;

// Problem dims (fixed)
#define NN 2048
#define DD 512
#define HH 256
#define LL 16
#define L2 32

#define OFF_MU (NN * NN)
#define OFF_LV (NN * NN + NN * LL)

#define SLOPE 0.01f
#define AA_C ((1.0f + SLOPE) * 0.5f)
#define BB_C ((1.0f - SLOPE) * 0.5f)

// Scratch (device globals; no allocation allowed)
__device__ float g_part[4 * NN * HH];   // split-K partials for K1/K2 (8MB)
__device__ float g_Y[NN * HH];          // X @ W1^T
__device__ float g_Hh[NN * HH];         // leaky(A @ Y + b1)
__device__ float g_G[NN * L2];          // Hh @ [Wmu;Wlv]^T
__device__ float g_MLp[16][NN * L2];    // split-K partials of A @ G
__device__ float g_P[NN * L2];          // Z @ Wd1[:, :16]^T
__device__ float g_Qb[NN * L2];         // Z @ Wd1[:, 16:]^T + bd1
__device__ float g_S[NN];               // 0.505 * sum_h w_h P[i,h]
__device__ float g_T[NN];               // 0.505 * sum_h w_h Qb[j,h] + bd2

// ---------------------------------------------------------------------------
// f32x2 packed helpers (FFMA2 only reachable via PTX)
// ---------------------------------------------------------------------------
__device__ __forceinline__ ull pack2(float x) {
    ull r; asm("mov.b64 %0, {%1, %1};" : "=l"(r) : "f"(x)); return r;
}
__device__ __forceinline__ float2 unpack2(ull v) {
    float2 r; asm("mov.b64 {%0, %1}, %2;" : "=f"(r.x), "=f"(r.y) : "l"(v)); return r;
}
__device__ __forceinline__ void fma2(ull& d, ull a, ull b) {
    asm("fma.rn.f32x2 %0, %1, %2, %0;" : "+l"(d) : "l"(a), "l"(b));
}
__device__ __forceinline__ ull add2(ull a, ull b) {
    ull r; asm("add.rn.f32x2 %0, %1, %2;" : "=l"(r) : "l"(a), "l"(b)); return r;
}

// ---------------------------------------------------------------------------
// sgemm128: 128x128 tile, 256 threads, 8x8 micro-tile (f32x2), BK=16,
// split-K via blockIdx.z (writes partials, no epilogue math).
// BT=false: C = A[M,K] @ B[K,N];  BT=true: C = A[M,K] @ B'[N,K]^T
// ---------------------------------------------------------------------------
template <bool BT>
__global__ __launch_bounds__(256) void sgemm128(
    const float* __restrict__ A, const float* __restrict__ B,
    float* __restrict__ Cpart, int M, int N, int K, int kslice)
{
    __shared__ float As[16][132];
    __shared__ float Bs[16][132];

    const int tid = threadIdx.x;
    const int m0 = blockIdx.y * 128;
    const int n0 = blockIdx.x * 128;
    const int k0 = blockIdx.z * kslice;

    // A loader: rows ar, ar+64; 4 k's each; store transposed As[k][m]
    const int ar = tid >> 2;
    const int ac = (tid & 3) << 2;
    const float* Ap0 = A + (size_t)(m0 + ar) * K + k0 + ac;
    const float* Ap1 = Ap0 + (size_t)64 * K;

    // B loader
    int br, bc;
    const float *Bp0, *Bp1;
    if (BT) {
        br = tid >> 2; bc = (tid & 3) << 2;
        Bp0 = B + (size_t)(n0 + br) * K + k0 + bc;
        Bp1 = Bp0 + (size_t)64 * K;
    } else {
        br = tid >> 5; bc = (tid & 31) << 2;
        Bp0 = B + (size_t)(k0 + br) * N + n0 + bc;
        Bp1 = Bp0 + (size_t)8 * N;
    }

    const int tx = tid & 15;
    const int ty = tid >> 4;

    ull acc[8][4];
    #pragma unroll
    for (int u = 0; u < 8; u++)
        #pragma unroll
        for (int p = 0; p < 4; p++) acc[u][p] = 0ull;

    float4 a0 = *(const float4*)Ap0;
    float4 a1 = *(const float4*)Ap1;
    float4 b0 = *(const float4*)Bp0;
    float4 b1 = *(const float4*)Bp1;

    for (int kt = 0; kt < kslice; kt += 16) {
        As[ac + 0][ar] = a0.x; As[ac + 1][ar] = a0.y;
        As[ac + 2][ar] = a0.z; As[ac + 3][ar] = a0.w;
        As[ac + 0][ar + 64] = a1.x; As[ac + 1][ar + 64] = a1.y;
        As[ac + 2][ar + 64] = a1.z; As[ac + 3][ar + 64] = a1.w;
        if (BT) {
            Bs[bc + 0][br] = b0.x; Bs[bc + 1][br] = b0.y;
            Bs[bc + 2][br] = b0.z; Bs[bc + 3][br] = b0.w;
            Bs[bc + 0][br + 64] = b1.x; Bs[bc + 1][br + 64] = b1.y;
            Bs[bc + 2][br + 64] = b1.z; Bs[bc + 3][br + 64] = b1.w;
        } else {
            *(float4*)&Bs[br][bc] = b0;
            *(float4*)&Bs[br + 8][bc] = b1;
        }
        __syncthreads();

        if (kt + 16 < kslice) {
            a0 = *(const float4*)(Ap0 + kt + 16);
            a1 = *(const float4*)(Ap1 + kt + 16);
            if (BT) {
                b0 = *(const float4*)(Bp0 + kt + 16);
                b1 = *(const float4*)(Bp1 + kt + 16);
            } else {
                b0 = *(const float4*)(Bp0 + (size_t)(kt + 16) * N);
                b1 = *(const float4*)(Bp1 + (size_t)(kt + 16) * N);
            }
        }

        #pragma unroll
        for (int kk = 0; kk < 16; kk++) {
            float4 av0 = *(const float4*)&As[kk][ty * 4];
            float4 av1 = *(const float4*)&As[kk][64 + ty * 4];
            ulonglong2 bv0 = *(const ulonglong2*)&Bs[kk][tx * 4];
            ulonglong2 bv1 = *(const ulonglong2*)&Bs[kk][64 + tx * 4];
            ull pa[8];
            pa[0] = pack2(av0.x); pa[1] = pack2(av0.y);
            pa[2] = pack2(av0.z); pa[3] = pack2(av0.w);
            pa[4] = pack2(av1.x); pa[5] = pack2(av1.y);
            pa[6] = pack2(av1.z); pa[7] = pack2(av1.w);
            #pragma unroll
            for (int u = 0; u < 8; u++) {
                fma2(acc[u][0], pa[u], bv0.x);
                fma2(acc[u][1], pa[u], bv0.y);
                fma2(acc[u][2], pa[u], bv1.x);
                fma2(acc[u][3], pa[u], bv1.y);
            }
        }
        __syncthreads();
    }

    float* Cz = Cpart + (size_t)blockIdx.z * M * N;
    #pragma unroll
    for (int u = 0; u < 8; u++) {
        int row = m0 + ((u < 4) ? (ty * 4 + u) : (64 + ty * 4 + u - 4));
        float2 c0 = unpack2(acc[u][0]);
        float2 c1 = unpack2(acc[u][1]);
        float2 c2 = unpack2(acc[u][2]);
        float2 c3 = unpack2(acc[u][3]);
        *(float4*)&Cz[(size_t)row * N + n0 + tx * 4] =
            make_float4(c0.x, c0.y, c1.x, c1.y);
        *(float4*)&Cz[(size_t)row * N + n0 + 64 + tx * 4] =
            make_float4(c2.x, c2.y, c3.x, c3.y);
    }
}

// ---------------------------------------------------------------------------
// reduce4: sum 4 split-K partials; optional bias + leaky.
// ---------------------------------------------------------------------------
template <bool LEAKY>
__global__ __launch_bounds__(256) void reduce4(
    const float* __restrict__ part, float* __restrict__ Cout,
    int MN, int N, const float* __restrict__ bias)
{
    int i = (blockIdx.x * 256 + threadIdx.x) * 4;
    if (i >= MN) return;
    float4 v0 = *(const float4*)&part[i];
    float4 v1 = *(const float4*)&part[MN + i];
    float4 v2 = *(const float4*)&part[2 * MN + i];
    float4 v3 = *(const float4*)&part[3 * MN + i];
    float v[4] = {v0.x + v1.x + v2.x + v3.x, v0.y + v1.y + v2.y + v3.y,
                  v0.z + v1.z + v2.z + v3.z, v0.w + v1.w + v2.w + v3.w};
    if (LEAKY) {
        int col = i & (N - 1);
        #pragma unroll
        for (int j = 0; j < 4; j++) {
            float t = v[j] + bias[col + j];
            v[j] = fmaxf(t, SLOPE * t);
        }
    }
    *(float4*)&Cout[i] = make_float4(v[0], v[1], v[2], v[3]);
}

// ---------------------------------------------------------------------------
// K3: G[n, c] = sum_k Hh[n,k] * Wcat[c,k]; Wcat = [Wmu; Wlv] (32 x 256)
// ---------------------------------------------------------------------------
__global__ __launch_bounds__(512) void k3_gmat(
    const float* __restrict__ Wmu, const float* __restrict__ Wlv)
{
    __shared__ float Ws[32][257];
    const int tid = threadIdx.x;
    for (int idx = tid; idx < 32 * 256; idx += 512) {
        int c = idx >> 8, k = idx & 255;
        Ws[c][k] = (c < 16) ? Wmu[c * 256 + k] : Wlv[(c - 16) * 256 + k];
    }
    __syncthreads();

    const int m = blockIdx.x * 16 + (tid >> 5);
    const int c = tid & 31;
    const float4* hrow = (const float4*)&g_Hh[(size_t)m * 256];
    float acc = 0.f;
    #pragma unroll 4
    for (int k4 = 0; k4 < 64; k4++) {
        float4 h = hrow[k4];
        acc = fmaf(h.x, Ws[c][k4 * 4 + 0], acc);
        acc = fmaf(h.y, Ws[c][k4 * 4 + 1], acc);
        acc = fmaf(h.z, Ws[c][k4 * 4 + 2], acc);
        acc = fmaf(h.w, Ws[c][k4 * 4 + 3], acc);
    }
    g_G[m * 32 + c] = acc;
}

// ---------------------------------------------------------------------------
// K4: split-K (16) A @ G. Tile 256 rows x 32 cols, BK=16, 256 threads,
// micro 8x4 via f32x2.
// ---------------------------------------------------------------------------
__global__ __launch_bounds__(256) void k4_ag(const float* __restrict__ A)
{
    __shared__ float As[16][260];
    __shared__ float Bs[16][36];

    const int tid = threadIdx.x;
    const int m0 = blockIdx.x * 256;
    const int k0 = blockIdx.y * 128;    // kslice = 128

    const int ar = tid >> 2;            // 0..63
    const int ac = (tid & 3) << 2;
    const float* Ap = A + (size_t)(m0 + ar) * NN + k0 + ac;

    const int tx = tid & 7;             // col quad
    const int ty = tid >> 3;            // 0..31 row quads (ty*4, 128+ty*4)

    ull acc[8][2];
    #pragma unroll
    for (int u = 0; u < 8; u++) { acc[u][0] = 0ull; acc[u][1] = 0ull; }

    for (int kt = 0; kt < 128; kt += 16) {
        #pragma unroll
        for (int j = 0; j < 4; j++) {
            float4 a4 = *(const float4*)(Ap + (size_t)(64 * j) * NN + kt);
            As[ac + 0][ar + 64 * j] = a4.x; As[ac + 1][ar + 64 * j] = a4.y;
            As[ac + 2][ar + 64 * j] = a4.z; As[ac + 3][ar + 64 * j] = a4.w;
        }
        if (tid < 128) {
            int brr = tid >> 3, bcc = (tid & 7) << 2;
            *(float4*)&Bs[brr][bcc] =
                *(const float4*)&g_G[(size_t)(k0 + kt + brr) * 32 + bcc];
        }
        __syncthreads();

        #pragma unroll
        for (int kk = 0; kk < 16; kk++) {
            float4 av0 = *(const float4*)&As[kk][ty * 4];
            float4 av1 = *(const float4*)&As[kk][128 + ty * 4];
            ulonglong2 bv = *(const ulonglong2*)&Bs[kk][tx * 4];
            ull pa[8];
            pa[0] = pack2(av0.x); pa[1] = pack2(av0.y);
            pa[2] = pack2(av0.z); pa[3] = pack2(av0.w);
            pa[4] = pack2(av1.x); pa[5] = pack2(av1.y);
            pa[6] = pack2(av1.z); pa[7] = pack2(av1.w);
            #pragma unroll
            for (int u = 0; u < 8; u++) {
                fma2(acc[u][0], pa[u], bv.x);
                fma2(acc[u][1], pa[u], bv.y);
            }
        }
        __syncthreads();
    }

    float* outp = g_MLp[blockIdx.y];
    #pragma unroll
    for (int u = 0; u < 8; u++) {
        int row = m0 + ((u < 4) ? (ty * 4 + u) : (128 + ty * 4 + u - 4));
        float2 c0 = unpack2(acc[u][0]);
        float2 c1 = unpack2(acc[u][1]);
        *(float4*)&outp[(size_t)row * 32 + tx * 4] =
            make_float4(c0.x, c0.y, c1.x, c1.y);
    }
}

// ---------------------------------------------------------------------------
// K5: reduce 16 split-K partials, biases, mu/logvar out, reparameterize,
//     P/Qb, and rank-1 decoder terms S_i / T_j.
// ---------------------------------------------------------------------------
__global__ __launch_bounds__(256) void k5_epi(
    const float* __restrict__ eps, const float* __restrict__ bmu,
    const float* __restrict__ blv, const float* __restrict__ Wd1,
    const float* __restrict__ bd1, const float* __restrict__ Wd2,
    const float* __restrict__ bd2, float* __restrict__ out)
{
    __shared__ float mls[8][32];
    __shared__ float zs[8][16];
    const int r = threadIdx.x >> 5;
    const int c = threadIdx.x & 31;
    const int n = blockIdx.x * 8 + r;
    const size_t o = (size_t)n * 32 + c;

    float v = 0.f;
    #pragma unroll
    for (int s = 0; s < 16; s++) v += g_MLp[s][o];

    if (c < 16) {
        v += bmu[c];
        out[OFF_MU + n * 16 + c] = v;
    } else {
        v += blv[c - 16];
        out[OFF_LV + n * 16 + (c - 16)] = v;
    }
    mls[r][c] = v;
    __syncthreads();

    if (c < 16) {
        float z = mls[r][c] + eps[n * 16 + c] * expf(0.5f * mls[r][16 + c]);
        zs[r][c] = z;
    }
    __syncthreads();

    float p = 0.f, q = 0.f;
    #pragma unroll
    for (int l = 0; l < 16; l++) {
        float z = zs[r][l];
        p = fmaf(z, Wd1[c * 32 + l], p);
        q = fmaf(z, Wd1[c * 32 + 16 + l], q);
    }
    float qb = q + bd1[c];
    g_P[o] = p;
    g_Qb[o] = qb;

    float w = Wd2[c];
    float sv = w * p;
    float tv = w * qb;
    #pragma unroll
    for (int off = 16; off >= 1; off >>= 1) {
        sv += __shfl_xor_sync(0xffffffffu, sv, off);
        tv += __shfl_xor_sync(0xffffffffu, tv, off);
    }
    if (c == 0) {
        g_S[n] = AA_C * sv;
        g_T[n] = AA_C * tv + bd2[0];
    }
}

// ---------------------------------------------------------------------------
// Software sigmoid (no MUFU)
// ---------------------------------------------------------------------------
__device__ __forceinline__ float fast_sigmoid(float x)
{
    float ax = fminf(fabsf(x), 30.0f);
    float t = ax * -1.4426950408889634f;
    float tr = t + 12582912.0f;
    int ki = __float_as_int(tr) - 0x4B400000;
    float f = t - (tr - 12582912.0f);
    float p = 1.3333558e-3f;
    p = fmaf(p, f, 9.6181291e-3f);
    p = fmaf(p, f, 5.5504109e-2f);
    p = fmaf(p, f, 2.4022651e-1f);
    p = fmaf(p, f, 6.9314718e-1f);
    p = fmaf(p, f, 1.0f);
    float rr = p * __int_as_float((ki + 127) << 23);
    float d = 1.0f + rr;
    float y = __int_as_float(0x7EF311C3 - __float_as_int(d));
    y = y * (2.0f - d * y);
    y = y * (2.0f - d * y);
    y = y * (2.0f - d * y);
    return (x >= 0.0f) ? y : rr * y;
}

// ---------------------------------------------------------------------------
// K6: decoder via leaky split: logit = S_i + T_j + sum_h (BB*w_h)*|P_ih+Qb_jh|
// 64x64 tile, 256 threads, micro 4x4 (f32x2 packed over j-pairs).
// ---------------------------------------------------------------------------
__global__ __launch_bounds__(256) void k6_decoder(
    float* __restrict__ out, const float* __restrict__ Wd2)
{
    __shared__ float Pt[32][68];   // [h][i]
    __shared__ float Qt[32][68];   // [h][j]
    __shared__ ull ws2s[32];
    __shared__ float Ss[64];
    __shared__ float Ts[64];

    const int tid = threadIdx.x;
    const int i0 = blockIdx.y * 64;
    const int j0 = blockIdx.x * 64;

    #pragma unroll
    for (int t = tid; t < 512; t += 256) {
        int r = t >> 3, c4 = (t & 7) << 2;
        float4 pv = *(const float4*)&g_P[(size_t)(i0 + r) * 32 + c4];
        Pt[c4 + 0][r] = pv.x; Pt[c4 + 1][r] = pv.y;
        Pt[c4 + 2][r] = pv.z; Pt[c4 + 3][r] = pv.w;
        float4 qv = *(const float4*)&g_Qb[(size_t)(j0 + r) * 32 + c4];
        Qt[c4 + 0][r] = qv.x; Qt[c4 + 1][r] = qv.y;
        Qt[c4 + 2][r] = qv.z; Qt[c4 + 3][r] = qv.w;
    }
    if (tid < 32) ws2s[tid] = pack2(BB_C * Wd2[tid]);
    if (tid < 64) { Ss[tid] = g_S[i0 + tid]; Ts[tid] = g_T[j0 + tid]; }
    __syncthreads();

    const int tx = tid & 15;   // col quad j0 + tx*4
    const int ty = tid >> 4;   // row quad i0 + ty*4

    ull acc[4][2];
    #pragma unroll
    for (int u = 0; u < 4; u++) { acc[u][0] = 0ull; acc[u][1] = 0ull; }

    const ull AMASK = 0x7FFFFFFF7FFFFFFFull;
    #pragma unroll
    for (int h = 0; h < 32; h++) {
        float4 pv = *(const float4*)&Pt[h][ty * 4];
        ulonglong2 qv = *(const ulonglong2*)&Qt[h][tx * 4];
        ull w2 = ws2s[h];
        ull pd[4];
        pd[0] = pack2(pv.x); pd[1] = pack2(pv.y);
        pd[2] = pack2(pv.z); pd[3] = pack2(pv.w);
        #pragma unroll
        for (int u = 0; u < 4; u++) {
            ull t0 = add2(pd[u], qv.x) & AMASK;
            ull t1 = add2(pd[u], qv.y) & AMASK;
            fma2(acc[u][0], t0, w2);
            fma2(acc[u][1], t1, w2);
        }
    }

    #pragma unroll
    for (int u = 0; u < 4; u++) {
        int i = i0 + ty * 4 + u;
        float si = Ss[ty * 4 + u];
        float2 c0 = unpack2(acc[u][0]);
        float2 c1 = unpack2(acc[u][1]);
        float4 o4;
        o4.x = fast_sigmoid(c0.x + si + Ts[tx * 4 + 0]);
        o4.y = fast_sigmoid(c0.y + si + Ts[tx * 4 + 1]);
        o4.z = fast_sigmoid(c1.x + si + Ts[tx * 4 + 2]);
        o4.w = fast_sigmoid(c1.y + si + Ts[tx * 4 + 3]);
        *(float4*)&out[(size_t)i * NN + j0 + tx * 4] = o4;
    }
}

// ---------------------------------------------------------------------------
extern "C" void kernel_launch(void* const* d_in, const int* in_sizes, int n_in,
                              void* d_out, int out_size)
{
    const float* A_hat = (const float*)d_in[0];
    const float* X     = (const float*)d_in[1];
    const float* eps   = (const float*)d_in[2];
    const float* W1    = (const float*)d_in[3];
    const float* b1    = (const float*)d_in[4];
    const float* Wmu   = (const float*)d_in[5];
    const float* bmu   = (const float*)d_in[6];
    const float* Wlv   = (const float*)d_in[7];
    const float* blv   = (const float*)d_in[8];
    const float* Wd1   = (const float*)d_in[9];
    const float* bd1   = (const float*)d_in[10];
    const float* Wd2   = (const float*)d_in[11];
    const float* bd2   = (const float*)d_in[12];
    float* out = (float*)d_out;

    float* part = nullptr; cudaGetSymbolAddress((void**)&part, g_part);
    float* Y    = nullptr; cudaGetSymbolAddress((void**)&Y,    g_Y);
    float* Hh   = nullptr; cudaGetSymbolAddress((void**)&Hh,   g_Hh);

    // K1: part = X @ W1^T  (split-K 4, kslice 128)
    sgemm128<true><<<dim3(HH / 128, NN / 128, 4), 256>>>(X, W1, part, NN, HH, DD, DD / 4);
    reduce4<false><<<NN * HH / 1024, 256>>>(part, Y, NN * HH, HH, nullptr);
    // K2: part = A @ Y  (split-K 4, kslice 512)
    sgemm128<false><<<dim3(HH / 128, NN / 128, 4), 256>>>(A_hat, Y, part, NN, HH, NN, NN / 4);
    reduce4<true><<<NN * HH / 1024, 256>>>(part, Hh, NN * HH, HH, b1);
    // K3: G = Hh @ [Wmu;Wlv]^T
    k3_gmat<<<NN / 16, 512>>>(Wmu, Wlv);
    // K4: MLp = A @ G  (split-K 16)
    k4_ag<<<dim3(NN / 256, 16), 256>>>(A_hat);
    // K5: reduce + biases + mu/logvar + Z + P/Qb + S/T
    k5_epi<<<NN / 8, 256>>>(eps, bmu, blv, Wd1, bd1, Wd2, bd2, out);
    // K6: pairwise decoder
    k6_decoder<<<dim3(NN / 64, NN / 64), 256>>>(out, Wd2);
}

// round 4
// speedup vs baseline: 1.7388x; 1.3119x over previous
#include <cuda_runtime.h>
#include <cuda_bf16.h>
#include <mma.h>
#include <math.h>
#include <stdint.h>

using namespace nvcuda;

typedef unsigned long long ull;
typedef unsigned int uint;

// Problem dims (fixed)
#define NN 2048
#define DD 512
#define HH 256
#define LL 16
#define L2 32

#define OFF_MU (NN * NN)
#define OFF_LV (NN * NN + NN * LL)

#define SLOPE 0.01f
#define AA_C ((1.0f + SLOPE) * 0.5f)
#define BB_C ((1.0f - SLOPE) * 0.5f)

// Scratch (device globals; no allocation allowed)
__device__ float g_part[8 * NN * HH];          // split-K fp32 partials (16MB)
__device__ __nv_bfloat16 g_Yhi[NN * HH];       // Y = X@W1^T, bf16 split hi [2048,256]
__device__ __nv_bfloat16 g_Ylo[NN * HH];       // bf16 split lo
__device__ float g_G[NN * L2];                 // Hh @ [Wmu;Wlv]^T
__device__ float g_MLp[16][NN * L2];           // split-K partials of A @ G
__device__ float g_P[NN * L2];
__device__ float g_Qb[NN * L2];
__device__ float g_S[NN];
__device__ float g_T[NN];

// ---------------------------------------------------------------------------
// f32x2 packed helpers
// ---------------------------------------------------------------------------
__device__ __forceinline__ ull pack2(float x) {
    ull r; asm("mov.b64 %0, {%1, %1};" : "=l"(r) : "f"(x)); return r;
}
__device__ __forceinline__ float2 unpack2(ull v) {
    float2 r; asm("mov.b64 {%0, %1}, %2;" : "=f"(r.x), "=f"(r.y) : "l"(v)); return r;
}
__device__ __forceinline__ void fma2(ull& d, ull a, ull b) {
    asm("fma.rn.f32x2 %0, %1, %2, %0;" : "+l"(d) : "l"(a), "l"(b));
}
__device__ __forceinline__ ull add2(ull a, ull b) {
    ull r; asm("add.rn.f32x2 %0, %1, %2;" : "=l"(r) : "l"(a), "l"(b)); return r;
}

// bf16 split: (x0,x1) -> packed hi pair + packed lo pair (elem0 in low half)
__device__ __forceinline__ void split2(float x0, float x1, uint& hp, uint& lp) {
    asm("cvt.rn.bf16x2.f32 %0, %1, %2;" : "=r"(hp) : "f"(x1), "f"(x0));
    float h0 = __int_as_float(hp << 16);
    float h1 = __int_as_float(hp & 0xFFFF0000u);
    float l0 = x0 - h0, l1 = x1 - h1;
    asm("cvt.rn.bf16x2.f32 %0, %1, %2;" : "=r"(lp) : "f"(l1), "f"(l0));
}

template <bool C, class T, class F> struct cond_t { using type = T; };
template <class T, class F> struct cond_t<false, T, F> { using type = F; };

// ---------------------------------------------------------------------------
// wgemm: C_part[z] = A[M,K](fp32, split in-kernel) @ B
//   BMODE 0: B = fp32 [N,K] row-major (i.e. B^T; col_major fragments)  [K1]
//   BMODE 1: B = bf16 hi/lo [K,N] row-major (row_major fragments)      [K2]
// Block tile 128x128, 8 warps (warp tile 32x64), K-chunk 32, 3-MMA bf16 split.
// Writes fp32 partials Cpart[z][M][256].
// ---------------------------------------------------------------------------
template <int BMODE>
__global__ __launch_bounds__(256) void wgemm(
    const float* __restrict__ A, int lda,
    const float* __restrict__ Bf, int ldb,
    const __nv_bfloat16* __restrict__ Bhi, const __nv_bfloat16* __restrict__ Blo,
    int kslice, float* __restrict__ Cpart)
{
    __shared__ __nv_bfloat16 sAhi[128 * 40], sAlo[128 * 40];
    __shared__ __nv_bfloat16 sBhi[128 * 40], sBlo[128 * 40]; // mode1 uses [32][136]

    const int tid = threadIdx.x;
    const int wid = tid >> 5;
    const int wm = wid & 3;          // warp row (32 m)
    const int wn = wid >> 2;         // warp col (64 n)
    const int m0 = blockIdx.y * 128;
    const int n0 = blockIdx.x * 128;
    const int k0 = blockIdx.z * kslice;

    wmma::fragment<wmma::accumulator, 16, 16, 16, float> acc[2][4];
    #pragma unroll
    for (int i = 0; i < 2; i++)
        #pragma unroll
        for (int j = 0; j < 4; j++) wmma::fill_fragment(acc[i][j], 0.0f);

    using BLay = typename cond_t<BMODE == 0, wmma::col_major, wmma::row_major>::type;

    for (int kt = 0; kt < kslice; kt += 32) {
        // Stage A: 128 rows x 32 k, fp32 -> bf16 hi/lo
        #pragma unroll
        for (int it = 0; it < 4; it++) {
            int r = it * 32 + (tid >> 3);
            int c4 = (tid & 7) << 2;
            float4 v = *(const float4*)&A[(size_t)(m0 + r) * lda + k0 + kt + c4];
            uint h01, l01, h23, l23;
            split2(v.x, v.y, h01, l01);
            split2(v.z, v.w, h23, l23);
            *(uint2*)&sAhi[r * 40 + c4] = make_uint2(h01, h23);
            *(uint2*)&sAlo[r * 40 + c4] = make_uint2(l01, l23);
        }
        // Stage B
        if (BMODE == 0) {
            #pragma unroll
            for (int it = 0; it < 4; it++) {
                int r = it * 32 + (tid >> 3);      // n-local
                int c4 = (tid & 7) << 2;           // k-local
                float4 v = *(const float4*)&Bf[(size_t)(n0 + r) * ldb + k0 + kt + c4];
                uint h01, l01, h23, l23;
                split2(v.x, v.y, h01, l01);
                split2(v.z, v.w, h23, l23);
                *(uint2*)&sBhi[r * 40 + c4] = make_uint2(h01, h23);
                *(uint2*)&sBlo[r * 40 + c4] = make_uint2(l01, l23);
            }
        } else {
            #pragma unroll
            for (int it = 0; it < 2; it++) {
                int r = it * 16 + (tid >> 4);      // k-local
                int c8 = (tid & 15) << 3;          // n-local
                size_t gb = (size_t)(k0 + kt + r) * HH + n0 + c8;
                *(uint4*)&sBhi[r * 136 + c8] = *(const uint4*)&Bhi[gb];
                *(uint4*)&sBlo[r * 136 + c8] = *(const uint4*)&Blo[gb];
            }
        }
        __syncthreads();

        #pragma unroll
        for (int ks = 0; ks < 2; ks++) {
            wmma::fragment<wmma::matrix_a, 16, 16, 16, __nv_bfloat16, wmma::row_major> ah[2], al[2];
            wmma::fragment<wmma::matrix_b, 16, 16, 16, __nv_bfloat16, BLay> bh[4], bl[4];
            #pragma unroll
            for (int i = 0; i < 2; i++) {
                int row = wm * 32 + i * 16;
                wmma::load_matrix_sync(ah[i], &sAhi[row * 40 + ks * 16], 40);
                wmma::load_matrix_sync(al[i], &sAlo[row * 40 + ks * 16], 40);
            }
            #pragma unroll
            for (int j = 0; j < 4; j++) {
                int col = wn * 64 + j * 16;
                if (BMODE == 0) {
                    wmma::load_matrix_sync(bh[j], &sBhi[col * 40 + ks * 16], 40);
                    wmma::load_matrix_sync(bl[j], &sBlo[col * 40 + ks * 16], 40);
                } else {
                    wmma::load_matrix_sync(bh[j], &sBhi[(ks * 16) * 136 + col], 136);
                    wmma::load_matrix_sync(bl[j], &sBlo[(ks * 16) * 136 + col], 136);
                }
            }
            #pragma unroll
            for (int i = 0; i < 2; i++)
                #pragma unroll
                for (int j = 0; j < 4; j++) {
                    wmma::mma_sync(acc[i][j], ah[i], bh[j], acc[i][j]);
                    wmma::mma_sync(acc[i][j], ah[i], bl[j], acc[i][j]);
                    wmma::mma_sync(acc[i][j], al[i], bh[j], acc[i][j]);
                }
        }
        __syncthreads();
    }

    float* Cz = Cpart + (size_t)blockIdx.z * NN * HH;
    #pragma unroll
    for (int i = 0; i < 2; i++)
        #pragma unroll
        for (int j = 0; j < 4; j++) {
            float* dst = Cz + (size_t)(m0 + wm * 32 + i * 16) * HH + n0 + wn * 64 + j * 16;
            wmma::store_matrix_sync(dst, acc[i][j], HH, wmma::mem_row_major);
        }
}

// ---------------------------------------------------------------------------
// reduce_split: Y = sum of 4 partials, emitted as bf16 hi/lo pair arrays.
// ---------------------------------------------------------------------------
__global__ __launch_bounds__(256) void reduce_split(const float* __restrict__ part)
{
    const size_t S = (size_t)NN * HH;
    size_t i = ((size_t)blockIdx.x * 256 + threadIdx.x) * 4;
    float4 v0 = *(const float4*)&part[i];
    float4 v1 = *(const float4*)&part[S + i];
    float4 v2 = *(const float4*)&part[2 * S + i];
    float4 v3 = *(const float4*)&part[3 * S + i];
    float a = v0.x + v1.x + v2.x + v3.x;
    float b = v0.y + v1.y + v2.y + v3.y;
    float c = v0.z + v1.z + v2.z + v3.z;
    float d = v0.w + v1.w + v2.w + v3.w;
    uint h01, l01, h23, l23;
    split2(a, b, h01, l01);
    split2(c, d, h23, l23);
    *(uint2*)&g_Yhi[i] = make_uint2(h01, h23);
    *(uint2*)&g_Ylo[i] = make_uint2(l01, l23);
}

// ---------------------------------------------------------------------------
// K3: fuse 8-way split-K reduce + bias + leaky into Hh rows (smem), then
//     G[n, c] = sum_k Hh[n,k] * Wcat[c,k]
// ---------------------------------------------------------------------------
__global__ __launch_bounds__(512) void k3_gmat(
    const float* __restrict__ b1,
    const float* __restrict__ Wmu, const float* __restrict__ Wlv)
{
    __shared__ float Ws[32][257];
    __shared__ float Hrow[16][260];
    const int tid = threadIdx.x;
    for (int idx = tid; idx < 32 * 256; idx += 512) {
        int c = idx >> 8, k = idx & 255;
        Ws[c][k] = (c < 16) ? Wmu[c * 256 + k] : Wlv[(c - 16) * 256 + k];
    }
    const int m0 = blockIdx.x * 16;
    const size_t S = (size_t)NN * HH;
    for (int idx = tid; idx < 16 * 256; idx += 512) {
        int r = idx >> 8, k = idx & 255;
        size_t gi = (size_t)(m0 + r) * 256 + k;
        float v = b1[k];
        #pragma unroll
        for (int s = 0; s < 8; s++) v += g_part[s * S + gi];
        Hrow[r][k] = fmaxf(v, SLOPE * v);
    }
    __syncthreads();

    const int w = tid >> 5;
    const int c = tid & 31;
    const float4* hr = (const float4*)&Hrow[w][0];
    float acc = 0.f;
    #pragma unroll 4
    for (int k4 = 0; k4 < 64; k4++) {
        float4 h = hr[k4];
        acc = fmaf(h.x, Ws[c][k4 * 4 + 0], acc);
        acc = fmaf(h.y, Ws[c][k4 * 4 + 1], acc);
        acc = fmaf(h.z, Ws[c][k4 * 4 + 2], acc);
        acc = fmaf(h.w, Ws[c][k4 * 4 + 3], acc);
    }
    g_G[(m0 + w) * 32 + c] = acc;
}

// ---------------------------------------------------------------------------
// K4: split-K (16) A @ G. Tile 256 x 32, BK=16, micro 8x4 via f32x2.
// ---------------------------------------------------------------------------
__global__ __launch_bounds__(256) void k4_ag(const float* __restrict__ A)
{
    __shared__ float As[16][260];
    __shared__ float Bs[16][36];

    const int tid = threadIdx.x;
    const int m0 = blockIdx.x * 256;
    const int k0 = blockIdx.y * 128;

    const int ar = tid >> 2;
    const int ac = (tid & 3) << 2;
    const float* Ap = A + (size_t)(m0 + ar) * NN + k0 + ac;

    const int tx = tid & 7;
    const int ty = tid >> 3;

    ull acc[8][2];
    #pragma unroll
    for (int u = 0; u < 8; u++) { acc[u][0] = 0ull; acc[u][1] = 0ull; }

    for (int kt = 0; kt < 128; kt += 16) {
        #pragma unroll
        for (int j = 0; j < 4; j++) {
            float4 a4 = *(const float4*)(Ap + (size_t)(64 * j) * NN + kt);
            As[ac + 0][ar + 64 * j] = a4.x; As[ac + 1][ar + 64 * j] = a4.y;
            As[ac + 2][ar + 64 * j] = a4.z; As[ac + 3][ar + 64 * j] = a4.w;
        }
        if (tid < 128) {
            int brr = tid >> 3, bcc = (tid & 7) << 2;
            *(float4*)&Bs[brr][bcc] =
                *(const float4*)&g_G[(size_t)(k0 + kt + brr) * 32 + bcc];
        }
        __syncthreads();

        #pragma unroll
        for (int kk = 0; kk < 16; kk++) {
            float4 av0 = *(const float4*)&As[kk][ty * 4];
            float4 av1 = *(const float4*)&As[kk][128 + ty * 4];
            ulonglong2 bv = *(const ulonglong2*)&Bs[kk][tx * 4];
            ull pa[8];
            pa[0] = pack2(av0.x); pa[1] = pack2(av0.y);
            pa[2] = pack2(av0.z); pa[3] = pack2(av0.w);
            pa[4] = pack2(av1.x); pa[5] = pack2(av1.y);
            pa[6] = pack2(av1.z); pa[7] = pack2(av1.w);
            #pragma unroll
            for (int u = 0; u < 8; u++) {
                fma2(acc[u][0], pa[u], bv.x);
                fma2(acc[u][1], pa[u], bv.y);
            }
        }
        __syncthreads();
    }

    float* outp = g_MLp[blockIdx.y];
    #pragma unroll
    for (int u = 0; u < 8; u++) {
        int row = m0 + ((u < 4) ? (ty * 4 + u) : (128 + ty * 4 + u - 4));
        float2 c0 = unpack2(acc[u][0]);
        float2 c1 = unpack2(acc[u][1]);
        *(float4*)&outp[(size_t)row * 32 + tx * 4] =
            make_float4(c0.x, c0.y, c1.x, c1.y);
    }
}

// ---------------------------------------------------------------------------
// K5: reduce 16 partials, biases, mu/logvar, reparameterize, P/Qb, S/T.
// ---------------------------------------------------------------------------
__global__ __launch_bounds__(256) void k5_epi(
    const float* __restrict__ eps, const float* __restrict__ bmu,
    const float* __restrict__ blv, const float* __restrict__ Wd1,
    const float* __restrict__ bd1, const float* __restrict__ Wd2,
    const float* __restrict__ bd2, float* __restrict__ out)
{
    __shared__ float mls[8][32];
    __shared__ float zs[8][16];
    const int r = threadIdx.x >> 5;
    const int c = threadIdx.x & 31;
    const int n = blockIdx.x * 8 + r;
    const size_t o = (size_t)n * 32 + c;

    float v = 0.f;
    #pragma unroll
    for (int s = 0; s < 16; s++) v += g_MLp[s][o];

    if (c < 16) {
        v += bmu[c];
        out[OFF_MU + n * 16 + c] = v;
    } else {
        v += blv[c - 16];
        out[OFF_LV + n * 16 + (c - 16)] = v;
    }
    mls[r][c] = v;
    __syncthreads();

    if (c < 16) {
        float z = mls[r][c] + eps[n * 16 + c] * expf(0.5f * mls[r][16 + c]);
        zs[r][c] = z;
    }
    __syncthreads();

    float p = 0.f, q = 0.f;
    #pragma unroll
    for (int l = 0; l < 16; l++) {
        float z = zs[r][l];
        p = fmaf(z, Wd1[c * 32 + l], p);
        q = fmaf(z, Wd1[c * 32 + 16 + l], q);
    }
    float qb = q + bd1[c];
    g_P[o] = p;
    g_Qb[o] = qb;

    float w = Wd2[c];
    float sv = w * p;
    float tv = w * qb;
    #pragma unroll
    for (int off = 16; off >= 1; off >>= 1) {
        sv += __shfl_xor_sync(0xffffffffu, sv, off);
        tv += __shfl_xor_sync(0xffffffffu, tv, off);
    }
    if (c == 0) {
        g_S[n] = AA_C * sv;
        g_T[n] = AA_C * tv + bd2[0];
    }
}

// ---------------------------------------------------------------------------
// Software sigmoid (no MUFU)
// ---------------------------------------------------------------------------
__device__ __forceinline__ float fast_sigmoid(float x)
{
    float ax = fminf(fabsf(x), 30.0f);
    float t = ax * -1.4426950408889634f;
    float tr = t + 12582912.0f;
    int ki = __float_as_int(tr) - 0x4B400000;
    float f = t - (tr - 12582912.0f);
    float p = 1.3333558e-3f;
    p = fmaf(p, f, 9.6181291e-3f);
    p = fmaf(p, f, 5.5504109e-2f);
    p = fmaf(p, f, 2.4022651e-1f);
    p = fmaf(p, f, 6.9314718e-1f);
    p = fmaf(p, f, 1.0f);
    float rr = p * __int_as_float((ki + 127) << 23);
    float d = 1.0f + rr;
    float y = __int_as_float(0x7EF311C3 - __float_as_int(d));
    y = y * (2.0f - d * y);
    y = y * (2.0f - d * y);
    y = y * (2.0f - d * y);
    return (x >= 0.0f) ? y : rr * y;
}

// ---------------------------------------------------------------------------
// K6: decoder via leaky split: logit = S_i + T_j + sum_h (BB*w_h)*|P_ih+Qb_jh|
// ---------------------------------------------------------------------------
__global__ __launch_bounds__(256) void k6_decoder(
    float* __restrict__ out, const float* __restrict__ Wd2)
{
    __shared__ float Pt[32][68];
    __shared__ float Qt[32][68];
    __shared__ ull ws2s[32];
    __shared__ float Ss[64];
    __shared__ float Ts[64];

    const int tid = threadIdx.x;
    const int i0 = blockIdx.y * 64;
    const int j0 = blockIdx.x * 64;

    #pragma unroll
    for (int t = tid; t < 512; t += 256) {
        int r = t >> 3, c4 = (t & 7) << 2;
        float4 pv = *(const float4*)&g_P[(size_t)(i0 + r) * 32 + c4];
        Pt[c4 + 0][r] = pv.x; Pt[c4 + 1][r] = pv.y;
        Pt[c4 + 2][r] = pv.z; Pt[c4 + 3][r] = pv.w;
        float4 qv = *(const float4*)&g_Qb[(size_t)(j0 + r) * 32 + c4];
        Qt[c4 + 0][r] = qv.x; Qt[c4 + 1][r] = qv.y;
        Qt[c4 + 2][r] = qv.z; Qt[c4 + 3][r] = qv.w;
    }
    if (tid < 32) ws2s[tid] = pack2(BB_C * Wd2[tid]);
    if (tid < 64) { Ss[tid] = g_S[i0 + tid]; Ts[tid] = g_T[j0 + tid]; }
    __syncthreads();

    const int tx = tid & 15;
    const int ty = tid >> 4;

    ull acc[4][2];
    #pragma unroll
    for (int u = 0; u < 4; u++) { acc[u][0] = 0ull; acc[u][1] = 0ull; }

    const ull AMASK = 0x7FFFFFFF7FFFFFFFull;
    #pragma unroll
    for (int h = 0; h < 32; h++) {
        float4 pv = *(const float4*)&Pt[h][ty * 4];
        ulonglong2 qv = *(const ulonglong2*)&Qt[h][tx * 4];
        ull w2 = ws2s[h];
        ull pd[4];
        pd[0] = pack2(pv.x); pd[1] = pack2(pv.y);
        pd[2] = pack2(pv.z); pd[3] = pack2(pv.w);
        #pragma unroll
        for (int u = 0; u < 4; u++) {
            ull t0 = add2(pd[u], qv.x) & AMASK;
            ull t1 = add2(pd[u], qv.y) & AMASK;
            fma2(acc[u][0], t0, w2);
            fma2(acc[u][1], t1, w2);
        }
    }

    #pragma unroll
    for (int u = 0; u < 4; u++) {
        int i = i0 + ty * 4 + u;
        float si = Ss[ty * 4 + u];
        float2 c0 = unpack2(acc[u][0]);
        float2 c1 = unpack2(acc[u][1]);
        float4 o4;
        o4.x = fast_sigmoid(c0.x + si + Ts[tx * 4 + 0]);
        o4.y = fast_sigmoid(c0.y + si + Ts[tx * 4 + 1]);
        o4.z = fast_sigmoid(c1.x + si + Ts[tx * 4 + 2]);
        o4.w = fast_sigmoid(c1.y + si + Ts[tx * 4 + 3]);
        *(float4*)&out[(size_t)i * NN + j0 + tx * 4] = o4;
    }
}

// ---------------------------------------------------------------------------
extern "C" void kernel_launch(void* const* d_in, const int* in_sizes, int n_in,
                              void* d_out, int out_size)
{
    const float* A_hat = (const float*)d_in[0];
    const float* X     = (const float*)d_in[1];
    const float* eps   = (const float*)d_in[2];
    const float* W1    = (const float*)d_in[3];
    const float* b1    = (const float*)d_in[4];
    const float* Wmu   = (const float*)d_in[5];
    const float* bmu   = (const float*)d_in[6];
    const float* Wlv   = (const float*)d_in[7];
    const float* blv   = (const float*)d_in[8];
    const float* Wd1   = (const float*)d_in[9];
    const float* bd1   = (const float*)d_in[10];
    const float* Wd2   = (const float*)d_in[11];
    const float* bd2   = (const float*)d_in[12];
    float* out = (float*)d_out;

    float* part = nullptr; cudaGetSymbolAddress((void**)&part, g_part);
    __nv_bfloat16* Yhi = nullptr; cudaGetSymbolAddress((void**)&Yhi, g_Yhi);
    __nv_bfloat16* Ylo = nullptr; cudaGetSymbolAddress((void**)&Ylo, g_Ylo);

    // K1: part[0..3] = X @ W1^T  (split-K 4, kslice 128)
    wgemm<0><<<dim3(2, 16, 4), 256>>>(X, DD, W1, DD, nullptr, nullptr, DD / 4, part);
    // Y(hi/lo) = sum partials, bf16-split
    reduce_split<<<NN * HH / 1024, 256>>>(part);
    // K2: part[0..7] = A_hat @ Y  (split-K 8, kslice 256)
    wgemm<1><<<dim3(2, 16, 8), 256>>>(A_hat, NN, nullptr, 0, Yhi, Ylo, NN / 8, part);
    // K3: reduce 8 partials + b1 + leaky -> Hh (smem) -> G
    k3_gmat<<<NN / 16, 512>>>(b1, Wmu, Wlv);
    // K4: MLp = A_hat @ G  (split-K 16)
    k4_ag<<<dim3(NN / 256, 16), 256>>>(A_hat);
    // K5: reduce + biases + mu/logvar + Z + P/Qb + S/T
    k5_epi<<<NN / 8, 256>>>(eps, bmu, blv, Wd1, bd1, Wd2, bd2, out);
    // K6: pairwise decoder
    k6_decoder<<<dim3(NN / 64, NN / 64), 256>>>(out, Wd2);
}

// round 5
// speedup vs baseline: 1.8944x; 1.0894x over previous
#include <cuda_runtime.h>
#include <cuda_bf16.h>
#include <mma.h>
#include <math.h>
#include <stdint.h>

using namespace nvcuda;

typedef unsigned long long ull;
typedef unsigned int uint;

// Problem dims (fixed)
#define NN 2048
#define DD 512
#define HH 256
#define LL 16
#define L2 32

#define OFF_MU (NN * NN)
#define OFF_LV (NN * NN + NN * LL)

#define SLOPE 0.01f
#define AA_C ((1.0f + SLOPE) * 0.5f)
#define BB_C ((1.0f - SLOPE) * 0.5f)

// Scratch (device globals; no allocation allowed)
__device__ float g_part[4 * NN * HH];          // split-K fp32 partials (8MB)
__device__ __nv_bfloat16 g_Yhi[NN * HH];       // Y = X@W1^T, bf16 split hi [2048,256]
__device__ __nv_bfloat16 g_Ylo[NN * HH];       // bf16 split lo
__device__ float g_G[NN * L2];                 // Hh @ [Wmu;Wlv]^T
__device__ float g_MLp[16][NN * L2];           // split-K partials of A @ G
__device__ float g_P[NN * L2];
__device__ float g_Qb[NN * L2];
__device__ float g_S[NN];
__device__ float g_T[NN];

// ---------------------------------------------------------------------------
// f32x2 packed helpers
// ---------------------------------------------------------------------------
__device__ __forceinline__ ull pack2(float x) {
    ull r; asm("mov.b64 %0, {%1, %1};" : "=l"(r) : "f"(x)); return r;
}
__device__ __forceinline__ float2 unpack2(ull v) {
    float2 r; asm("mov.b64 {%0, %1}, %2;" : "=f"(r.x), "=f"(r.y) : "l"(v)); return r;
}
__device__ __forceinline__ void fma2(ull& d, ull a, ull b) {
    asm("fma.rn.f32x2 %0, %1, %2, %0;" : "+l"(d) : "l"(a), "l"(b));
}
__device__ __forceinline__ ull add2(ull a, ull b) {
    ull r; asm("add.rn.f32x2 %0, %1, %2;" : "=l"(r) : "l"(a), "l"(b)); return r;
}

// bf16 split: (x0,x1) -> packed hi pair + packed lo pair (elem0 in low half)
__device__ __forceinline__ void split2(float x0, float x1, uint& hp, uint& lp) {
    asm("cvt.rn.bf16x2.f32 %0, %1, %2;" : "=r"(hp) : "f"(x1), "f"(x0));
    float h0 = __int_as_float(hp << 16);
    float h1 = __int_as_float(hp & 0xFFFF0000u);
    float l0 = x0 - h0, l1 = x1 - h1;
    asm("cvt.rn.bf16x2.f32 %0, %1, %2;" : "=r"(lp) : "f"(l1), "f"(l0));
}

template <bool C, class T, class F> struct cond_t { using type = T; };
template <class T, class F> struct cond_t<false, T, F> { using type = F; };

// ---------------------------------------------------------------------------
// wgemm: C_part[z] = A[M,K](fp32, split in-kernel) @ B
//   BMODE 0: B = fp32 [N,K] row-major (i.e. B^T; col_major fragments)  [K1]
//   BMODE 1: B = bf16 hi/lo [K,N] row-major (row_major fragments)      [K2]
// Block tile 128x128, 8 warps (warp tile 32x64), K-chunk 32, 3-MMA bf16 split.
// Writes fp32 partials Cpart[z][M][256].
// ---------------------------------------------------------------------------
template <int BMODE>
__global__ __launch_bounds__(256) void wgemm(
    const float* __restrict__ A, int lda,
    const float* __restrict__ Bf, int ldb,
    const __nv_bfloat16* __restrict__ Bhi, const __nv_bfloat16* __restrict__ Blo,
    int kslice, float* __restrict__ Cpart)
{
    __shared__ __nv_bfloat16 sAhi[128 * 40], sAlo[128 * 40];
    __shared__ __nv_bfloat16 sBhi[128 * 40], sBlo[128 * 40]; // mode1 uses [32][136]

    const int tid = threadIdx.x;
    const int wid = tid >> 5;
    const int wm = wid & 3;          // warp row (32 m)
    const int wn = wid >> 2;         // warp col (64 n)
    const int m0 = blockIdx.y * 128;
    const int n0 = blockIdx.x * 128;
    const int k0 = blockIdx.z * kslice;

    wmma::fragment<wmma::accumulator, 16, 16, 16, float> acc[2][4];
    #pragma unroll
    for (int i = 0; i < 2; i++)
        #pragma unroll
        for (int j = 0; j < 4; j++) wmma::fill_fragment(acc[i][j], 0.0f);

    using BLay = typename cond_t<BMODE == 0, wmma::col_major, wmma::row_major>::type;

    for (int kt = 0; kt < kslice; kt += 32) {
        // Stage A: 128 rows x 32 k, fp32 -> bf16 hi/lo
        #pragma unroll
        for (int it = 0; it < 4; it++) {
            int r = it * 32 + (tid >> 3);
            int c4 = (tid & 7) << 2;
            float4 v = *(const float4*)&A[(size_t)(m0 + r) * lda + k0 + kt + c4];
            uint h01, l01, h23, l23;
            split2(v.x, v.y, h01, l01);
            split2(v.z, v.w, h23, l23);
            *(uint2*)&sAhi[r * 40 + c4] = make_uint2(h01, h23);
            *(uint2*)&sAlo[r * 40 + c4] = make_uint2(l01, l23);
        }
        // Stage B
        if (BMODE == 0) {
            #pragma unroll
            for (int it = 0; it < 4; it++) {
                int r = it * 32 + (tid >> 3);      // n-local
                int c4 = (tid & 7) << 2;           // k-local
                float4 v = *(const float4*)&Bf[(size_t)(n0 + r) * ldb + k0 + kt + c4];
                uint h01, l01, h23, l23;
                split2(v.x, v.y, h01, l01);
                split2(v.z, v.w, h23, l23);
                *(uint2*)&sBhi[r * 40 + c4] = make_uint2(h01, h23);
                *(uint2*)&sBlo[r * 40 + c4] = make_uint2(l01, l23);
            }
        } else {
            #pragma unroll
            for (int it = 0; it < 2; it++) {
                int r = it * 16 + (tid >> 4);      // k-local
                int c8 = (tid & 15) << 3;          // n-local
                size_t gb = (size_t)(k0 + kt + r) * HH + n0 + c8;
                *(uint4*)&sBhi[r * 136 + c8] = *(const uint4*)&Bhi[gb];
                *(uint4*)&sBlo[r * 136 + c8] = *(const uint4*)&Blo[gb];
            }
        }
        __syncthreads();

        #pragma unroll
        for (int ks = 0; ks < 2; ks++) {
            wmma::fragment<wmma::matrix_a, 16, 16, 16, __nv_bfloat16, wmma::row_major> ah[2], al[2];
            wmma::fragment<wmma::matrix_b, 16, 16, 16, __nv_bfloat16, BLay> bh[4], bl[4];
            #pragma unroll
            for (int i = 0; i < 2; i++) {
                int row = wm * 32 + i * 16;
                wmma::load_matrix_sync(ah[i], &sAhi[row * 40 + ks * 16], 40);
                wmma::load_matrix_sync(al[i], &sAlo[row * 40 + ks * 16], 40);
            }
            #pragma unroll
            for (int j = 0; j < 4; j++) {
                int col = wn * 64 + j * 16;
                if (BMODE == 0) {
                    wmma::load_matrix_sync(bh[j], &sBhi[col * 40 + ks * 16], 40);
                    wmma::load_matrix_sync(bl[j], &sBlo[col * 40 + ks * 16], 40);
                } else {
                    wmma::load_matrix_sync(bh[j], &sBhi[(ks * 16) * 136 + col], 136);
                    wmma::load_matrix_sync(bl[j], &sBlo[(ks * 16) * 136 + col], 136);
                }
            }
            #pragma unroll
            for (int i = 0; i < 2; i++)
                #pragma unroll
                for (int j = 0; j < 4; j++) {
                    wmma::mma_sync(acc[i][j], ah[i], bh[j], acc[i][j]);
                    wmma::mma_sync(acc[i][j], ah[i], bl[j], acc[i][j]);
                    wmma::mma_sync(acc[i][j], al[i], bh[j], acc[i][j]);
                }
        }
        __syncthreads();
    }

    float* Cz = Cpart + (size_t)blockIdx.z * NN * HH;
    #pragma unroll
    for (int i = 0; i < 2; i++)
        #pragma unroll
        for (int j = 0; j < 4; j++) {
            float* dst = Cz + (size_t)(m0 + wm * 32 + i * 16) * HH + n0 + wn * 64 + j * 16;
            wmma::store_matrix_sync(dst, acc[i][j], HH, wmma::mem_row_major);
        }
}

// ---------------------------------------------------------------------------
// reduce_split: Y = sum of 4 partials, emitted as bf16 hi/lo pair arrays.
// ---------------------------------------------------------------------------
__global__ __launch_bounds__(256) void reduce_split(const float* __restrict__ part)
{
    const size_t S = (size_t)NN * HH;
    size_t i = ((size_t)blockIdx.x * 256 + threadIdx.x) * 4;
    float4 v0 = *(const float4*)&part[i];
    float4 v1 = *(const float4*)&part[S + i];
    float4 v2 = *(const float4*)&part[2 * S + i];
    float4 v3 = *(const float4*)&part[3 * S + i];
    float a = v0.x + v1.x + v2.x + v3.x;
    float b = v0.y + v1.y + v2.y + v3.y;
    float c = v0.z + v1.z + v2.z + v3.z;
    float d = v0.w + v1.w + v2.w + v3.w;
    uint h01, l01, h23, l23;
    split2(a, b, h01, l01);
    split2(c, d, h23, l23);
    *(uint2*)&g_Yhi[i] = make_uint2(h01, h23);
    *(uint2*)&g_Ylo[i] = make_uint2(l01, l23);
}

// ---------------------------------------------------------------------------
// K3: fuse 4-way split-K reduce + bias + leaky into Hh rows (smem), then
//     G[n, c] = sum_k Hh[n,k] * Wcat[c,k].
// 256 blocks x 256 threads, 8 rows/block (warp-per-row) for full-chip occupancy.
// ---------------------------------------------------------------------------
__global__ __launch_bounds__(256) void k3_gmat(
    const float* __restrict__ b1,
    const float* __restrict__ Wmu, const float* __restrict__ Wlv)
{
    __shared__ float Ws[32][260];
    __shared__ float Hrow[8][260];
    const int tid = threadIdx.x;
    const int m0 = blockIdx.x * 8;
    const size_t S = (size_t)NN * HH;

    // Load Wcat [32 x 256] as float4
    #pragma unroll
    for (int it = 0; it < 8; it++) {
        int idx = tid + it * 256;           // 0..2047
        int c = idx >> 6, k4 = (idx & 63) << 2;
        const float* src = (c < 16) ? &Wmu[c * 256 + k4] : &Wlv[(c - 16) * 256 + k4];
        *(float4*)&Ws[c][k4] = *(const float4*)src;
    }
    // Reduce 4 partial slices + bias + leaky -> Hrow [8 x 256]
    #pragma unroll
    for (int it = 0; it < 2; it++) {
        int idx = tid + it * 256;           // 0..511
        int r = idx >> 6, k4 = (idx & 63) << 2;
        size_t gi = (size_t)(m0 + r) * 256 + k4;
        float4 v0 = *(const float4*)&g_part[gi];
        float4 v1 = *(const float4*)&g_part[S + gi];
        float4 v2 = *(const float4*)&g_part[2 * S + gi];
        float4 v3 = *(const float4*)&g_part[3 * S + gi];
        float4 bb = *(const float4*)&b1[k4];
        float a = v0.x + v1.x + v2.x + v3.x + bb.x;
        float b = v0.y + v1.y + v2.y + v3.y + bb.y;
        float c = v0.z + v1.z + v2.z + v3.z + bb.z;
        float d = v0.w + v1.w + v2.w + v3.w + bb.w;
        Hrow[r][k4 + 0] = fmaxf(a, SLOPE * a);
        Hrow[r][k4 + 1] = fmaxf(b, SLOPE * b);
        Hrow[r][k4 + 2] = fmaxf(c, SLOPE * c);
        Hrow[r][k4 + 3] = fmaxf(d, SLOPE * d);
    }
    __syncthreads();

    // warp w -> row (m0+w); lanes -> 32 output channels
    const int w = tid >> 5;
    const int c = tid & 31;
    float acc = 0.f;
    #pragma unroll 8
    for (int k4 = 0; k4 < 64; k4++) {
        float4 h = *(const float4*)&Hrow[w][k4 * 4];
        float4 ww = *(const float4*)&Ws[c][k4 * 4];
        acc = fmaf(h.x, ww.x, acc);
        acc = fmaf(h.y, ww.y, acc);
        acc = fmaf(h.z, ww.z, acc);
        acc = fmaf(h.w, ww.w, acc);
    }
    g_G[(m0 + w) * 32 + c] = acc;
}

// ---------------------------------------------------------------------------
// K4: split-K (16) A @ G. Tile 256 x 32, BK=16, micro 8x4 via f32x2.
// ---------------------------------------------------------------------------
__global__ __launch_bounds__(256) void k4_ag(const float* __restrict__ A)
{
    __shared__ float As[16][260];
    __shared__ float Bs[16][36];

    const int tid = threadIdx.x;
    const int m0 = blockIdx.x * 256;
    const int k0 = blockIdx.y * 128;

    const int ar = tid >> 2;
    const int ac = (tid & 3) << 2;
    const float* Ap = A + (size_t)(m0 + ar) * NN + k0 + ac;

    const int tx = tid & 7;
    const int ty = tid >> 3;

    ull acc[8][2];
    #pragma unroll
    for (int u = 0; u < 8; u++) { acc[u][0] = 0ull; acc[u][1] = 0ull; }

    for (int kt = 0; kt < 128; kt += 16) {
        #pragma unroll
        for (int j = 0; j < 4; j++) {
            float4 a4 = *(const float4*)(Ap + (size_t)(64 * j) * NN + kt);
            As[ac + 0][ar + 64 * j] = a4.x; As[ac + 1][ar + 64 * j] = a4.y;
            As[ac + 2][ar + 64 * j] = a4.z; As[ac + 3][ar + 64 * j] = a4.w;
        }
        if (tid < 128) {
            int brr = tid >> 3, bcc = (tid & 7) << 2;
            *(float4*)&Bs[brr][bcc] =
                *(const float4*)&g_G[(size_t)(k0 + kt + brr) * 32 + bcc];
        }
        __syncthreads();

        #pragma unroll
        for (int kk = 0; kk < 16; kk++) {
            float4 av0 = *(const float4*)&As[kk][ty * 4];
            float4 av1 = *(const float4*)&As[kk][128 + ty * 4];
            ulonglong2 bv = *(const ulonglong2*)&Bs[kk][tx * 4];
            ull pa[8];
            pa[0] = pack2(av0.x); pa[1] = pack2(av0.y);
            pa[2] = pack2(av0.z); pa[3] = pack2(av0.w);
            pa[4] = pack2(av1.x); pa[5] = pack2(av1.y);
            pa[6] = pack2(av1.z); pa[7] = pack2(av1.w);
            #pragma unroll
            for (int u = 0; u < 8; u++) {
                fma2(acc[u][0], pa[u], bv.x);
                fma2(acc[u][1], pa[u], bv.y);
            }
        }
        __syncthreads();
    }

    float* outp = g_MLp[blockIdx.y];
    #pragma unroll
    for (int u = 0; u < 8; u++) {
        int row = m0 + ((u < 4) ? (ty * 4 + u) : (128 + ty * 4 + u - 4));
        float2 c0 = unpack2(acc[u][0]);
        float2 c1 = unpack2(acc[u][1]);
        *(float4*)&outp[(size_t)row * 32 + tx * 4] =
            make_float4(c0.x, c0.y, c1.x, c1.y);
    }
}

// ---------------------------------------------------------------------------
// K5: reduce 16 partials, biases, mu/logvar, reparameterize, P/Qb, S/T.
// ---------------------------------------------------------------------------
__global__ __launch_bounds__(256) void k5_epi(
    const float* __restrict__ eps, const float* __restrict__ bmu,
    const float* __restrict__ blv, const float* __restrict__ Wd1,
    const float* __restrict__ bd1, const float* __restrict__ Wd2,
    const float* __restrict__ bd2, float* __restrict__ out)
{
    __shared__ float mls[8][32];
    __shared__ float zs[8][16];
    const int r = threadIdx.x >> 5;
    const int c = threadIdx.x & 31;
    const int n = blockIdx.x * 8 + r;
    const size_t o = (size_t)n * 32 + c;

    float v = 0.f;
    #pragma unroll
    for (int s = 0; s < 16; s++) v += g_MLp[s][o];

    if (c < 16) {
        v += bmu[c];
        out[OFF_MU + n * 16 + c] = v;
    } else {
        v += blv[c - 16];
        out[OFF_LV + n * 16 + (c - 16)] = v;
    }
    mls[r][c] = v;
    __syncthreads();

    if (c < 16) {
        float z = mls[r][c] + eps[n * 16 + c] * expf(0.5f * mls[r][16 + c]);
        zs[r][c] = z;
    }
    __syncthreads();

    float p = 0.f, q = 0.f;
    #pragma unroll
    for (int l = 0; l < 16; l++) {
        float z = zs[r][l];
        p = fmaf(z, Wd1[c * 32 + l], p);
        q = fmaf(z, Wd1[c * 32 + 16 + l], q);
    }
    float qb = q + bd1[c];
    g_P[o] = p;
    g_Qb[o] = qb;

    float w = Wd2[c];
    float sv = w * p;
    float tv = w * qb;
    #pragma unroll
    for (int off = 16; off >= 1; off >>= 1) {
        sv += __shfl_xor_sync(0xffffffffu, sv, off);
        tv += __shfl_xor_sync(0xffffffffu, tv, off);
    }
    if (c == 0) {
        g_S[n] = AA_C * sv;
        g_T[n] = AA_C * tv + bd2[0];
    }
}

// ---------------------------------------------------------------------------
// Software sigmoid (no MUFU)
// ---------------------------------------------------------------------------
__device__ __forceinline__ float fast_sigmoid(float x)
{
    float ax = fminf(fabsf(x), 30.0f);
    float t = ax * -1.4426950408889634f;
    float tr = t + 12582912.0f;
    int ki = __float_as_int(tr) - 0x4B400000;
    float f = t - (tr - 12582912.0f);
    float p = 1.3333558e-3f;
    p = fmaf(p, f, 9.6181291e-3f);
    p = fmaf(p, f, 5.5504109e-2f);
    p = fmaf(p, f, 2.4022651e-1f);
    p = fmaf(p, f, 6.9314718e-1f);
    p = fmaf(p, f, 1.0f);
    float rr = p * __int_as_float((ki + 127) << 23);
    float d = 1.0f + rr;
    float y = __int_as_float(0x7EF311C3 - __float_as_int(d));
    y = y * (2.0f - d * y);
    y = y * (2.0f - d * y);
    y = y * (2.0f - d * y);
    return (x >= 0.0f) ? y : rr * y;
}

// ---------------------------------------------------------------------------
// K6: decoder via leaky split: logit = S_i + T_j + sum_h (BB*w_h)*|P_ih+Qb_jh|
// ---------------------------------------------------------------------------
__global__ __launch_bounds__(256) void k6_decoder(
    float* __restrict__ out, const float* __restrict__ Wd2)
{
    __shared__ float Pt[32][68];
    __shared__ float Qt[32][68];
    __shared__ ull ws2s[32];
    __shared__ float Ss[64];
    __shared__ float Ts[64];

    const int tid = threadIdx.x;
    const int i0 = blockIdx.y * 64;
    const int j0 = blockIdx.x * 64;

    #pragma unroll
    for (int t = tid; t < 512; t += 256) {
        int r = t >> 3, c4 = (t & 7) << 2;
        float4 pv = *(const float4*)&g_P[(size_t)(i0 + r) * 32 + c4];
        Pt[c4 + 0][r] = pv.x; Pt[c4 + 1][r] = pv.y;
        Pt[c4 + 2][r] = pv.z; Pt[c4 + 3][r] = pv.w;
        float4 qv = *(const float4*)&g_Qb[(size_t)(j0 + r) * 32 + c4];
        Qt[c4 + 0][r] = qv.x; Qt[c4 + 1][r] = qv.y;
        Qt[c4 + 2][r] = qv.z; Qt[c4 + 3][r] = qv.w;
    }
    if (tid < 32) ws2s[tid] = pack2(BB_C * Wd2[tid]);
    if (tid < 64) { Ss[tid] = g_S[i0 + tid]; Ts[tid] = g_T[j0 + tid]; }
    __syncthreads();

    const int tx = tid & 15;
    const int ty = tid >> 4;

    ull acc[4][2];
    #pragma unroll
    for (int u = 0; u < 4; u++) { acc[u][0] = 0ull; acc[u][1] = 0ull; }

    const ull AMASK = 0x7FFFFFFF7FFFFFFFull;
    #pragma unroll
    for (int h = 0; h < 32; h++) {
        float4 pv = *(const float4*)&Pt[h][ty * 4];
        ulonglong2 qv = *(const ulonglong2*)&Qt[h][tx * 4];
        ull w2 = ws2s[h];
        ull pd[4];
        pd[0] = pack2(pv.x); pd[1] = pack2(pv.y);
        pd[2] = pack2(pv.z); pd[3] = pack2(pv.w);
        #pragma unroll
        for (int u = 0; u < 4; u++) {
            ull t0 = add2(pd[u], qv.x) & AMASK;
            ull t1 = add2(pd[u], qv.y) & AMASK;
            fma2(acc[u][0], t0, w2);
            fma2(acc[u][1], t1, w2);
        }
    }

    #pragma unroll
    for (int u = 0; u < 4; u++) {
        int i = i0 + ty * 4 + u;
        float si = Ss[ty * 4 + u];
        float2 c0 = unpack2(acc[u][0]);
        float2 c1 = unpack2(acc[u][1]);
        float4 o4;
        o4.x = fast_sigmoid(c0.x + si + Ts[tx * 4 + 0]);
        o4.y = fast_sigmoid(c0.y + si + Ts[tx * 4 + 1]);
        o4.z = fast_sigmoid(c1.x + si + Ts[tx * 4 + 2]);
        o4.w = fast_sigmoid(c1.y + si + Ts[tx * 4 + 3]);
        *(float4*)&out[(size_t)i * NN + j0 + tx * 4] = o4;
    }
}

// ---------------------------------------------------------------------------
extern "C" void kernel_launch(void* const* d_in, const int* in_sizes, int n_in,
                              void* d_out, int out_size)
{
    const float* A_hat = (const float*)d_in[0];
    const float* X     = (const float*)d_in[1];
    const float* eps   = (const float*)d_in[2];
    const float* W1    = (const float*)d_in[3];
    const float* b1    = (const float*)d_in[4];
    const float* Wmu   = (const float*)d_in[5];
    const float* bmu   = (const float*)d_in[6];
    const float* Wlv   = (const float*)d_in[7];
    const float* blv   = (const float*)d_in[8];
    const float* Wd1   = (const float*)d_in[9];
    const float* bd1   = (const float*)d_in[10];
    const float* Wd2   = (const float*)d_in[11];
    const float* bd2   = (const float*)d_in[12];
    float* out = (float*)d_out;

    float* part = nullptr; cudaGetSymbolAddress((void**)&part, g_part);
    __nv_bfloat16* Yhi = nullptr; cudaGetSymbolAddress((void**)&Yhi, g_Yhi);
    __nv_bfloat16* Ylo = nullptr; cudaGetSymbolAddress((void**)&Ylo, g_Ylo);

    // K1: part[0..3] = X @ W1^T  (split-K 4, kslice 128)
    wgemm<0><<<dim3(2, 16, 4), 256>>>(X, DD, W1, DD, nullptr, nullptr, DD / 4, part);
    // Y(hi/lo) = sum partials, bf16-split
    reduce_split<<<NN * HH / 1024, 256>>>(part);
    // K2: part[0..3] = A_hat @ Y  (split-K 4, kslice 512)
    wgemm<1><<<dim3(2, 16, 4), 256>>>(A_hat, NN, nullptr, 0, Yhi, Ylo, NN / 4, part);
    // K3: reduce 4 partials + b1 + leaky -> Hh (smem) -> G
    k3_gmat<<<NN / 8, 256>>>(b1, Wmu, Wlv);
    // K4: MLp = A_hat @ G  (split-K 16)
    k4_ag<<<dim3(NN / 256, 16), 256>>>(A_hat);
    // K5: reduce + biases + mu/logvar + Z + P/Qb + S/T
    k5_epi<<<NN / 8, 256>>>(eps, bmu, blv, Wd1, bd1, Wd2, bd2, out);
    // K6: pairwise decoder
    k6_decoder<<<dim3(NN / 64, NN / 64), 256>>>(out, Wd2);
}

// round 6
// speedup vs baseline: 1.9017x; 1.0039x over previous
#include <cuda_runtime.h>
#include <cuda_bf16.h>
#include <mma.h>
#include <math.h>
#include <stdint.h>

using namespace nvcuda;

typedef unsigned long long ull;
typedef unsigned int uint;

// Problem dims (fixed)
#define NN 2048
#define DD 512
#define HH 256
#define LL 16
#define L2 32

#define OFF_MU (NN * NN)
#define OFF_LV (NN * NN + NN * LL)

#define SLOPE 0.01f
#define AA_C ((1.0f + SLOPE) * 0.5f)
#define BB_C ((1.0f - SLOPE) * 0.5f)

// Scratch (device globals; no allocation allowed)
__device__ float g_part[4 * NN * HH];          // split-K fp32 partials (8MB)
__device__ __nv_bfloat16 g_Yhi[NN * HH];       // Y = X@W1^T, bf16 split hi
__device__ __nv_bfloat16 g_Ylo[NN * HH];       // bf16 split lo
__device__ float g_Hh[NN * HH];                // leaky(A@Y + b1) fp32 (2MB)
__device__ float g_G[NN * L2];                 // Hh @ [Wmu;Wlv]^T
__device__ float g_MLp[16][NN * L2];           // split-K partials of A @ G
__device__ float g_P[NN * L2];
__device__ float g_Qb[NN * L2];
__device__ float g_S[NN];
__device__ float g_T[NN];

// ---------------------------------------------------------------------------
// f32x2 packed helpers
// ---------------------------------------------------------------------------
__device__ __forceinline__ ull pack2(float x) {
    ull r; asm("mov.b64 %0, {%1, %1};" : "=l"(r) : "f"(x)); return r;
}
__device__ __forceinline__ float2 unpack2(ull v) {
    float2 r; asm("mov.b64 {%0, %1}, %2;" : "=f"(r.x), "=f"(r.y) : "l"(v)); return r;
}
__device__ __forceinline__ void fma2(ull& d, ull a, ull b) {
    asm("fma.rn.f32x2 %0, %1, %2, %0;" : "+l"(d) : "l"(a), "l"(b));
}
__device__ __forceinline__ ull add2(ull a, ull b) {
    ull r; asm("add.rn.f32x2 %0, %1, %2;" : "=l"(r) : "l"(a), "l"(b)); return r;
}

// bf16 split: (x0,x1) -> packed hi pair + packed lo pair (elem0 in low half)
__device__ __forceinline__ void split2(float x0, float x1, uint& hp, uint& lp) {
    asm("cvt.rn.bf16x2.f32 %0, %1, %2;" : "=r"(hp) : "f"(x1), "f"(x0));
    float h0 = __int_as_float(hp << 16);
    float h1 = __int_as_float(hp & 0xFFFF0000u);
    float l0 = x0 - h0, l1 = x1 - h1;
    asm("cvt.rn.bf16x2.f32 %0, %1, %2;" : "=r"(lp) : "f"(l1), "f"(l0));
}

template <bool C, class T, class F> struct cond_t { using type = T; };
template <class T, class F> struct cond_t<false, T, F> { using type = F; };

// ---------------------------------------------------------------------------
// wgemm: C_part[z] = A[M,K](fp32, split in-kernel) @ B
//   BMODE 0: B = fp32 [N,K] row-major (col_major fragments)  [K1]
//   BMODE 1: B = bf16 hi/lo [K,N] row-major (row_major frags) [K2]
// Block tile 128x128, 8 warps (warp tile 32x64), K-chunk 32, 3-MMA bf16 split.
// Register prefetch of next chunk's global loads overlaps DRAM with MMA.
// ---------------------------------------------------------------------------
template <int BMODE>
__global__ __launch_bounds__(256) void wgemm(
    const float* __restrict__ A, int lda,
    const float* __restrict__ Bf, int ldb,
    const __nv_bfloat16* __restrict__ Bhi, const __nv_bfloat16* __restrict__ Blo,
    int kslice, float* __restrict__ Cpart)
{
    __shared__ __nv_bfloat16 sAhi[128 * 40], sAlo[128 * 40];
    __shared__ __nv_bfloat16 sBhi[128 * 40], sBlo[128 * 40]; // mode1 uses [32][136]

    const int tid = threadIdx.x;
    const int wid = tid >> 5;
    const int wm = wid & 3;
    const int wn = wid >> 2;
    const int m0 = blockIdx.y * 128;
    const int n0 = blockIdx.x * 128;
    const int k0 = blockIdx.z * kslice;

    wmma::fragment<wmma::accumulator, 16, 16, 16, float> acc[2][4];
    #pragma unroll
    for (int i = 0; i < 2; i++)
        #pragma unroll
        for (int j = 0; j < 4; j++) wmma::fill_fragment(acc[i][j], 0.0f);

    using BLay = typename cond_t<BMODE == 0, wmma::col_major, wmma::row_major>::type;

    // Per-thread load coordinates
    const int arow = tid >> 3;               // A: rows arow + 32*it
    const int acol = (tid & 7) << 2;
    const int b0row = tid >> 3;              // mode0 B rows
    const int b0col = (tid & 7) << 2;
    const int b1row = tid >> 4;              // mode1 B k-local
    const int b1col = (tid & 15) << 3;

    float4 aR[4];
    float4 bR[4];
    uint4 bhR[2], blR[2];

    auto loadA = [&](int kt) {
        #pragma unroll
        for (int it = 0; it < 4; it++)
            aR[it] = *(const float4*)&A[(size_t)(m0 + it * 32 + arow) * lda + k0 + kt + acol];
    };
    auto loadB = [&](int kt) {
        if (BMODE == 0) {
            #pragma unroll
            for (int it = 0; it < 4; it++)
                bR[it] = *(const float4*)&Bf[(size_t)(n0 + it * 32 + b0row) * ldb + k0 + kt + b0col];
        } else {
            #pragma unroll
            for (int it = 0; it < 2; it++) {
                size_t gb = (size_t)(k0 + kt + it * 16 + b1row) * HH + n0 + b1col;
                bhR[it] = *(const uint4*)&Bhi[gb];
                blR[it] = *(const uint4*)&Blo[gb];
            }
        }
    };

    loadA(0);
    loadB(0);

    for (int kt = 0; kt < kslice; kt += 32) {
        // Convert + store staged registers to smem
        #pragma unroll
        for (int it = 0; it < 4; it++) {
            int r = it * 32 + arow;
            uint h01, l01, h23, l23;
            split2(aR[it].x, aR[it].y, h01, l01);
            split2(aR[it].z, aR[it].w, h23, l23);
            *(uint2*)&sAhi[r * 40 + acol] = make_uint2(h01, h23);
            *(uint2*)&sAlo[r * 40 + acol] = make_uint2(l01, l23);
        }
        if (BMODE == 0) {
            #pragma unroll
            for (int it = 0; it < 4; it++) {
                int r = it * 32 + b0row;
                uint h01, l01, h23, l23;
                split2(bR[it].x, bR[it].y, h01, l01);
                split2(bR[it].z, bR[it].w, h23, l23);
                *(uint2*)&sBhi[r * 40 + b0col] = make_uint2(h01, h23);
                *(uint2*)&sBlo[r * 40 + b0col] = make_uint2(l01, l23);
            }
        } else {
            #pragma unroll
            for (int it = 0; it < 2; it++) {
                int r = it * 16 + b1row;
                *(uint4*)&sBhi[r * 136 + b1col] = bhR[it];
                *(uint4*)&sBlo[r * 136 + b1col] = blR[it];
            }
        }
        __syncthreads();

        // Prefetch next chunk (LDGs in flight during MMA below)
        if (kt + 32 < kslice) {
            loadA(kt + 32);
            loadB(kt + 32);
        }

        #pragma unroll
        for (int ks = 0; ks < 2; ks++) {
            wmma::fragment<wmma::matrix_a, 16, 16, 16, __nv_bfloat16, wmma::row_major> ah[2], al[2];
            wmma::fragment<wmma::matrix_b, 16, 16, 16, __nv_bfloat16, BLay> bh[4], bl[4];
            #pragma unroll
            for (int i = 0; i < 2; i++) {
                int row = wm * 32 + i * 16;
                wmma::load_matrix_sync(ah[i], &sAhi[row * 40 + ks * 16], 40);
                wmma::load_matrix_sync(al[i], &sAlo[row * 40 + ks * 16], 40);
            }
            #pragma unroll
            for (int j = 0; j < 4; j++) {
                int col = wn * 64 + j * 16;
                if (BMODE == 0) {
                    wmma::load_matrix_sync(bh[j], &sBhi[col * 40 + ks * 16], 40);
                    wmma::load_matrix_sync(bl[j], &sBlo[col * 40 + ks * 16], 40);
                } else {
                    wmma::load_matrix_sync(bh[j], &sBhi[(ks * 16) * 136 + col], 136);
                    wmma::load_matrix_sync(bl[j], &sBlo[(ks * 16) * 136 + col], 136);
                }
            }
            #pragma unroll
            for (int i = 0; i < 2; i++)
                #pragma unroll
                for (int j = 0; j < 4; j++) {
                    wmma::mma_sync(acc[i][j], ah[i], bh[j], acc[i][j]);
                    wmma::mma_sync(acc[i][j], ah[i], bl[j], acc[i][j]);
                    wmma::mma_sync(acc[i][j], al[i], bh[j], acc[i][j]);
                }
        }
        __syncthreads();
    }

    float* Cz = Cpart + (size_t)blockIdx.z * NN * HH;
    #pragma unroll
    for (int i = 0; i < 2; i++)
        #pragma unroll
        for (int j = 0; j < 4; j++) {
            float* dst = Cz + (size_t)(m0 + wm * 32 + i * 16) * HH + n0 + wn * 64 + j * 16;
            wmma::store_matrix_sync(dst, acc[i][j], HH, wmma::mem_row_major);
        }
}

// ---------------------------------------------------------------------------
// reduce_split: Y = sum of 4 partials, emitted as bf16 hi/lo pair arrays.
// ---------------------------------------------------------------------------
__global__ __launch_bounds__(256) void reduce_split(const float* __restrict__ part)
{
    const size_t S = (size_t)NN * HH;
    size_t i = ((size_t)blockIdx.x * 256 + threadIdx.x) * 4;
    float4 v0 = *(const float4*)&part[i];
    float4 v1 = *(const float4*)&part[S + i];
    float4 v2 = *(const float4*)&part[2 * S + i];
    float4 v3 = *(const float4*)&part[3 * S + i];
    float a = v0.x + v1.x + v2.x + v3.x;
    float b = v0.y + v1.y + v2.y + v3.y;
    float c = v0.z + v1.z + v2.z + v3.z;
    float d = v0.w + v1.w + v2.w + v3.w;
    uint h01, l01, h23, l23;
    split2(a, b, h01, l01);
    split2(c, d, h23, l23);
    *(uint2*)&g_Yhi[i] = make_uint2(h01, h23);
    *(uint2*)&g_Ylo[i] = make_uint2(l01, l23);
}

// ---------------------------------------------------------------------------
// K3a: streaming reduce 4 partials + bias + leaky -> Hh fp32.
// ---------------------------------------------------------------------------
__global__ __launch_bounds__(256) void k3a_hh(const float* __restrict__ b1)
{
    const size_t S = (size_t)NN * HH;
    size_t i = ((size_t)blockIdx.x * 256 + threadIdx.x) * 4;
    int col = (int)(i & (HH - 1));
    float4 v0 = *(const float4*)&g_part[i];
    float4 v1 = *(const float4*)&g_part[S + i];
    float4 v2 = *(const float4*)&g_part[2 * S + i];
    float4 v3 = *(const float4*)&g_part[3 * S + i];
    float4 bb = *(const float4*)&b1[col];
    float a = v0.x + v1.x + v2.x + v3.x + bb.x;
    float b = v0.y + v1.y + v2.y + v3.y + bb.y;
    float c = v0.z + v1.z + v2.z + v3.z + bb.z;
    float d = v0.w + v1.w + v2.w + v3.w + bb.w;
    *(float4*)&g_Hh[i] = make_float4(fmaxf(a, SLOPE * a), fmaxf(b, SLOPE * b),
                                     fmaxf(c, SLOPE * c), fmaxf(d, SLOPE * d));
}

// ---------------------------------------------------------------------------
// K3b: G[n, c] = sum_k Hh[n,k] * Wcat[c,k]; warp-per-row, 8 rows/block.
// ---------------------------------------------------------------------------
__global__ __launch_bounds__(256) void k3b_gmat(
    const float* __restrict__ Wmu, const float* __restrict__ Wlv)
{
    __shared__ float Ws[32][260];
    const int tid = threadIdx.x;
    const int m0 = blockIdx.x * 8;

    #pragma unroll
    for (int it = 0; it < 8; it++) {
        int idx = tid + it * 256;
        int c = idx >> 6, k4 = (idx & 63) << 2;
        const float* src = (c < 16) ? &Wmu[c * 256 + k4] : &Wlv[(c - 16) * 256 + k4];
        *(float4*)&Ws[c][k4] = *(const float4*)src;
    }
    __syncthreads();

    const int w = tid >> 5;
    const int c = tid & 31;
    const float4* hr = (const float4*)&g_Hh[(size_t)(m0 + w) * 256];
    float acc = 0.f;
    #pragma unroll 8
    for (int k4 = 0; k4 < 64; k4++) {
        float4 h = hr[k4];
        float4 ww = *(const float4*)&Ws[c][k4 * 4];
        acc = fmaf(h.x, ww.x, acc);
        acc = fmaf(h.y, ww.y, acc);
        acc = fmaf(h.z, ww.z, acc);
        acc = fmaf(h.w, ww.w, acc);
    }
    g_G[(m0 + w) * 32 + c] = acc;
}

// ---------------------------------------------------------------------------
// K4: split-K (16) A @ G. Tile 256 x 32, BK=16, micro 8x4 via f32x2.
// ---------------------------------------------------------------------------
__global__ __launch_bounds__(256) void k4_ag(const float* __restrict__ A)
{
    __shared__ float As[16][260];
    __shared__ float Bs[16][36];

    const int tid = threadIdx.x;
    const int m0 = blockIdx.x * 256;
    const int k0 = blockIdx.y * 128;

    const int ar = tid >> 2;
    const int ac = (tid & 3) << 2;
    const float* Ap = A + (size_t)(m0 + ar) * NN + k0 + ac;

    const int tx = tid & 7;
    const int ty = tid >> 3;

    ull acc[8][2];
    #pragma unroll
    for (int u = 0; u < 8; u++) { acc[u][0] = 0ull; acc[u][1] = 0ull; }

    for (int kt = 0; kt < 128; kt += 16) {
        #pragma unroll
        for (int j = 0; j < 4; j++) {
            float4 a4 = *(const float4*)(Ap + (size_t)(64 * j) * NN + kt);
            As[ac + 0][ar + 64 * j] = a4.x; As[ac + 1][ar + 64 * j] = a4.y;
            As[ac + 2][ar + 64 * j] = a4.z; As[ac + 3][ar + 64 * j] = a4.w;
        }
        if (tid < 128) {
            int brr = tid >> 3, bcc = (tid & 7) << 2;
            *(float4*)&Bs[brr][bcc] =
                *(const float4*)&g_G[(size_t)(k0 + kt + brr) * 32 + bcc];
        }
        __syncthreads();

        #pragma unroll
        for (int kk = 0; kk < 16; kk++) {
            float4 av0 = *(const float4*)&As[kk][ty * 4];
            float4 av1 = *(const float4*)&As[kk][128 + ty * 4];
            ulonglong2 bv = *(const ulonglong2*)&Bs[kk][tx * 4];
            ull pa[8];
            pa[0] = pack2(av0.x); pa[1] = pack2(av0.y);
            pa[2] = pack2(av0.z); pa[3] = pack2(av0.w);
            pa[4] = pack2(av1.x); pa[5] = pack2(av1.y);
            pa[6] = pack2(av1.z); pa[7] = pack2(av1.w);
            #pragma unroll
            for (int u = 0; u < 8; u++) {
                fma2(acc[u][0], pa[u], bv.x);
                fma2(acc[u][1], pa[u], bv.y);
            }
        }
        __syncthreads();
    }

    float* outp = g_MLp[blockIdx.y];
    #pragma unroll
    for (int u = 0; u < 8; u++) {
        int row = m0 + ((u < 4) ? (ty * 4 + u) : (128 + ty * 4 + u - 4));
        float2 c0 = unpack2(acc[u][0]);
        float2 c1 = unpack2(acc[u][1]);
        *(float4*)&outp[(size_t)row * 32 + tx * 4] =
            make_float4(c0.x, c0.y, c1.x, c1.y);
    }
}

// ---------------------------------------------------------------------------
// K5: reduce 16 partials, biases, mu/logvar, reparameterize, P/Qb, S/T.
// ---------------------------------------------------------------------------
__global__ __launch_bounds__(256) void k5_epi(
    const float* __restrict__ eps, const float* __restrict__ bmu,
    const float* __restrict__ blv, const float* __restrict__ Wd1,
    const float* __restrict__ bd1, const float* __restrict__ Wd2,
    const float* __restrict__ bd2, float* __restrict__ out)
{
    __shared__ float mls[8][32];
    __shared__ float zs[8][16];
    const int r = threadIdx.x >> 5;
    const int c = threadIdx.x & 31;
    const int n = blockIdx.x * 8 + r;
    const size_t o = (size_t)n * 32 + c;

    float v = 0.f;
    #pragma unroll
    for (int s = 0; s < 16; s++) v += g_MLp[s][o];

    if (c < 16) {
        v += bmu[c];
        out[OFF_MU + n * 16 + c] = v;
    } else {
        v += blv[c - 16];
        out[OFF_LV + n * 16 + (c - 16)] = v;
    }
    mls[r][c] = v;
    __syncthreads();

    if (c < 16) {
        float z = mls[r][c] + eps[n * 16 + c] * expf(0.5f * mls[r][16 + c]);
        zs[r][c] = z;
    }
    __syncthreads();

    float p = 0.f, q = 0.f;
    #pragma unroll
    for (int l = 0; l < 16; l++) {
        float z = zs[r][l];
        p = fmaf(z, Wd1[c * 32 + l], p);
        q = fmaf(z, Wd1[c * 32 + 16 + l], q);
    }
    float qb = q + bd1[c];
    g_P[o] = p;
    g_Qb[o] = qb;

    float w = Wd2[c];
    float sv = w * p;
    float tv = w * qb;
    #pragma unroll
    for (int off = 16; off >= 1; off >>= 1) {
        sv += __shfl_xor_sync(0xffffffffu, sv, off);
        tv += __shfl_xor_sync(0xffffffffu, tv, off);
    }
    if (c == 0) {
        g_S[n] = AA_C * sv;
        g_T[n] = AA_C * tv + bd2[0];
    }
}

// ---------------------------------------------------------------------------
// Software sigmoid (no MUFU)
// ---------------------------------------------------------------------------
__device__ __forceinline__ float fast_sigmoid(float x)
{
    float ax = fminf(fabsf(x), 30.0f);
    float t = ax * -1.4426950408889634f;
    float tr = t + 12582912.0f;
    int ki = __float_as_int(tr) - 0x4B400000;
    float f = t - (tr - 12582912.0f);
    float p = 1.3333558e-3f;
    p = fmaf(p, f, 9.6181291e-3f);
    p = fmaf(p, f, 5.5504109e-2f);
    p = fmaf(p, f, 2.4022651e-1f);
    p = fmaf(p, f, 6.9314718e-1f);
    p = fmaf(p, f, 1.0f);
    float rr = p * __int_as_float((ki + 127) << 23);
    float d = 1.0f + rr;
    float y = __int_as_float(0x7EF311C3 - __float_as_int(d));
    y = y * (2.0f - d * y);
    y = y * (2.0f - d * y);
    y = y * (2.0f - d * y);
    return (x >= 0.0f) ? y : rr * y;
}

// ---------------------------------------------------------------------------
// K6: decoder via leaky split: logit = S_i + T_j + sum_h (BB*w_h)*|P_ih+Qb_jh|
// ---------------------------------------------------------------------------
__global__ __launch_bounds__(256) void k6_decoder(
    float* __restrict__ out, const float* __restrict__ Wd2)
{
    __shared__ float Pt[32][68];
    __shared__ float Qt[32][68];
    __shared__ ull ws2s[32];
    __shared__ float Ss[64];
    __shared__ float Ts[64];

    const int tid = threadIdx.x;
    const int i0 = blockIdx.y * 64;
    const int j0 = blockIdx.x * 64;

    #pragma unroll
    for (int t = tid; t < 512; t += 256) {
        int r = t >> 3, c4 = (t & 7) << 2;
        float4 pv = *(const float4*)&g_P[(size_t)(i0 + r) * 32 + c4];
        Pt[c4 + 0][r] = pv.x; Pt[c4 + 1][r] = pv.y;
        Pt[c4 + 2][r] = pv.z; Pt[c4 + 3][r] = pv.w;
        float4 qv = *(const float4*)&g_Qb[(size_t)(j0 + r) * 32 + c4];
        Qt[c4 + 0][r] = qv.x; Qt[c4 + 1][r] = qv.y;
        Qt[c4 + 2][r] = qv.z; Qt[c4 + 3][r] = qv.w;
    }
    if (tid < 32) ws2s[tid] = pack2(BB_C * Wd2[tid]);
    if (tid < 64) { Ss[tid] = g_S[i0 + tid]; Ts[tid] = g_T[j0 + tid]; }
    __syncthreads();

    const int tx = tid & 15;
    const int ty = tid >> 4;

    ull acc[4][2];
    #pragma unroll
    for (int u = 0; u < 4; u++) { acc[u][0] = 0ull; acc[u][1] = 0ull; }

    const ull AMASK = 0x7FFFFFFF7FFFFFFFull;
    #pragma unroll
    for (int h = 0; h < 32; h++) {
        float4 pv = *(const float4*)&Pt[h][ty * 4];
        ulonglong2 qv = *(const ulonglong2*)&Qt[h][tx * 4];
        ull w2 = ws2s[h];
        ull pd[4];
        pd[0] = pack2(pv.x); pd[1] = pack2(pv.y);
        pd[2] = pack2(pv.z); pd[3] = pack2(pv.w);
        #pragma unroll
        for (int u = 0; u < 4; u++) {
            ull t0 = add2(pd[u], qv.x) & AMASK;
            ull t1 = add2(pd[u], qv.y) & AMASK;
            fma2(acc[u][0], t0, w2);
            fma2(acc[u][1], t1, w2);
        }
    }

    #pragma unroll
    for (int u = 0; u < 4; u++) {
        int i = i0 + ty * 4 + u;
        float si = Ss[ty * 4 + u];
        float2 c0 = unpack2(acc[u][0]);
        float2 c1 = unpack2(acc[u][1]);
        float4 o4;
        o4.x = fast_sigmoid(c0.x + si + Ts[tx * 4 + 0]);
        o4.y = fast_sigmoid(c0.y + si + Ts[tx * 4 + 1]);
        o4.z = fast_sigmoid(c1.x + si + Ts[tx * 4 + 2]);
        o4.w = fast_sigmoid(c1.y + si + Ts[tx * 4 + 3]);
        *(float4*)&out[(size_t)i * NN + j0 + tx * 4] = o4;
    }
}

// ---------------------------------------------------------------------------
extern "C" void kernel_launch(void* const* d_in, const int* in_sizes, int n_in,
                              void* d_out, int out_size)
{
    const float* A_hat = (const float*)d_in[0];
    const float* X     = (const float*)d_in[1];
    const float* eps   = (const float*)d_in[2];
    const float* W1    = (const float*)d_in[3];
    const float* b1    = (const float*)d_in[4];
    const float* Wmu   = (const float*)d_in[5];
    const float* bmu   = (const float*)d_in[6];
    const float* Wlv   = (const float*)d_in[7];
    const float* blv   = (const float*)d_in[8];
    const float* Wd1   = (const float*)d_in[9];
    const float* bd1   = (const float*)d_in[10];
    const float* Wd2   = (const float*)d_in[11];
    const float* bd2   = (const float*)d_in[12];
    float* out = (float*)d_out;

    float* part = nullptr; cudaGetSymbolAddress((void**)&part, g_part);
    __nv_bfloat16* Yhi = nullptr; cudaGetSymbolAddress((void**)&Yhi, g_Yhi);
    __nv_bfloat16* Ylo = nullptr; cudaGetSymbolAddress((void**)&Ylo, g_Ylo);

    // K1: part[0..3] = X @ W1^T  (split-K 4, kslice 128)
    wgemm<0><<<dim3(2, 16, 4), 256>>>(X, DD, W1, DD, nullptr, nullptr, DD / 4, part);
    // Y(hi/lo) = sum partials, bf16-split
    reduce_split<<<NN * HH / 1024, 256>>>(part);
    // K2: part[0..3] = A_hat @ Y  (split-K 4, kslice 512)
    wgemm<1><<<dim3(2, 16, 4), 256>>>(A_hat, NN, nullptr, 0, Yhi, Ylo, NN / 4, part);
    // K3a: streaming reduce + b1 + leaky -> Hh
    k3a_hh<<<NN * HH / 1024, 256>>>(b1);
    // K3b: G = Hh @ [Wmu;Wlv]^T
    k3b_gmat<<<NN / 8, 256>>>(Wmu, Wlv);
    // K4: MLp = A_hat @ G  (split-K 16)
    k4_ag<<<dim3(NN / 256, 16), 256>>>(A_hat);
    // K5: reduce + biases + mu/logvar + Z + P/Qb + S/T
    k5_epi<<<NN / 8, 256>>>(eps, bmu, blv, Wd1, bd1, Wd2, bd2, out);
    // K6: pairwise decoder
    k6_decoder<<<dim3(NN / 64, NN / 64), 256>>>(out, Wd2);
}